// round 11
// baseline (speedup 1.0000x reference)
#include <cuda_runtime.h>
#include <cuda_bf16.h>

#define NSD 16
#define NVD 8
#define HED 32
#define DD  40
#define WND 640
#define MAXN 10000
#define MAXE 160000
#define EPSV 1e-5f
#define EC   128
#define TCB  128

// smem float offsets
#define OFF_W1  0
#define OFF_B1  1024
#define OFF_B2  1056
#define OFF_STG 1696            // stage: 128 rows x 69 (40 atom/ef + 24 coef + pad)
#define OFF_PAH 10528           // A pairs hi: 128 x 20 u32
#define OFF_PAL 13088
#define OFF_PBH 15648           // B pairs hi: 640 x 20 u32
#define OFF_PBL 28448
#define OFF_DSM 41248           // D tile: 128 x 129 f32
#define SM_FLT  57760
#define SM_TC   (SM_FLT * 4)

__device__ __constant__ float kC110 = 0.57735026918962576f;
__device__ __constant__ float kC111 = 0.70710678118654752f;

__device__ float    d_qnode[MAXN * DD];
__device__ float    d_attn [MAXE];
__device__ float    d_vedge[MAXE * DD];
__device__ unsigned d_nmax [MAXN];
__device__ float    d_denom[MAXN];
__device__ float    d_upd  [MAXN * DD];
__device__ float    d_ybuf [MAXN * DD];
__device__ float    d_gstats[48];
__device__ float    d_bnp  [48];

__device__ __forceinline__ unsigned encf(float f) {
    unsigned u = __float_as_uint(f);
    return (u & 0x80000000u) ? ~u : (u | 0x80000000u);
}
__device__ __forceinline__ float decf(unsigned u) {
    return (u & 0x80000000u) ? __uint_as_float(u ^ 0x80000000u) : __uint_as_float(~u);
}

__device__ __forceinline__ void mma16816(float& d0, float& d1, float& d2, float& d3,
                                         unsigned a0, unsigned a1, unsigned a2, unsigned a3,
                                         unsigned b0, unsigned b1) {
    asm volatile(
        "mma.sync.aligned.m16n8k16.row.col.f32.bf16.bf16.f32 "
        "{%0,%1,%2,%3}, {%4,%5,%6,%7}, {%8,%9}, {%0,%1,%2,%3};"
        : "+f"(d0), "+f"(d1), "+f"(d2), "+f"(d3)
        : "r"(a0), "r"(a1), "r"(a2), "r"(a3), "r"(b0), "r"(b1));
}
__device__ __forceinline__ unsigned pkbf(float x, float y) {
    __nv_bfloat16 bx = __float2bfloat16(x), by = __float2bfloat16(y);
    return (unsigned)__bfloat16_as_ushort(bx) | ((unsigned)__bfloat16_as_ushort(by) << 16);
}

__global__ void k_init(int n_nodes) {
    int i = blockIdx.x * blockDim.x + threadIdx.x;
    if (i < n_nodes * DD) d_upd[i] = 0.f;
    if (i < n_nodes) { d_denom[i] = 0.f; d_nmax[i] = 0u; }
    if (i < 48) d_gstats[i] = 0.f;
}

__global__ void k_qnode(const float* __restrict__ atom, const float* __restrict__ Wqs,
                        const float* __restrict__ Wqv, int n_nodes) {
    int n = blockIdx.x * blockDim.x + threadIdx.x;
    if (n >= n_nodes) return;
    const float* a = atom + n * DD;
    float qs[16], qv[24];
#pragma unroll
    for (int o = 0; o < 16; o++) qs[o] = 0.f;
#pragma unroll
    for (int c = 0; c < 24; c++) qv[c] = 0.f;
    for (int i = 0; i < 16; i++) {
        float x = __ldg(a + i);
#pragma unroll
        for (int o = 0; o < 16; o++) qs[o] = fmaf(x, __ldg(Wqs + i * 16 + o), qs[o]);
    }
    for (int i = 0; i < 8; i++) {
        float x0 = __ldg(a + 16 + 3 * i), x1 = __ldg(a + 17 + 3 * i), x2 = __ldg(a + 18 + 3 * i);
#pragma unroll
        for (int o = 0; o < 8; o++) {
            float w = __ldg(Wqv + i * 8 + o);
            qv[3 * o + 0] = fmaf(w, x0, qv[3 * o + 0]);
            qv[3 * o + 1] = fmaf(w, x1, qv[3 * o + 1]);
            qv[3 * o + 2] = fmaf(w, x2, qv[3 * o + 2]);
        }
    }
    float* q = d_qnode + n * DD;
#pragma unroll
    for (int o = 0; o < 16; o++) q[o] = qs[o];
#pragma unroll
    for (int c = 0; c < 24; c++) q[16 + c] = qv[c];
}

template <bool IS_K>
__global__ void __launch_bounds__(TCB, 1) k_edge_mma(
    const float* __restrict__ atom, const float* __restrict__ ef,
    const float* __restrict__ sh, const int* __restrict__ ei,
    const float* __restrict__ W1, const float* __restrict__ B1,
    const float* __restrict__ W2, const float* __restrict__ B2,
    int n_edges)
{
    extern __shared__ float sm[];
    float* sW1 = sm + OFF_W1;
    float* sB1 = sm + OFF_B1;
    float* sB2 = sm + OFF_B2;
    float* stage = sm + OFF_STG;
    unsigned* pAH = (unsigned*)(sm + OFF_PAH);
    unsigned* pAL = (unsigned*)(sm + OFF_PAL);
    unsigned* pBH = (unsigned*)(sm + OFF_PBH);
    unsigned* pBL = (unsigned*)(sm + OFF_PBL);
    float* Dsm = sm + OFF_DSM;

    const int t = threadIdx.x;
    const int w = t >> 5, lane = t & 31;
    const int grp = lane >> 2, lp = lane & 3;

    for (int i = t; i < 1024; i += TCB) sW1[i] = __ldg(W1 + i);
    if (t < 32) sB1[t] = __ldg(B1 + t);
    for (int i = t; i < WND; i += TCB) sB2[i] = __ldg(B2 + i);
    // W2 [32][640] -> k-pair-packed bf16 hi/lo: pB[n][p] = (W2[2p][n], W2[2p+1][n])
    for (int idx = t; idx < WND * 16; idx += TCB) {
        int n = idx >> 4, p = idx & 15;
        float w0 = __ldg(W2 + (2 * p) * WND + n);
        float w1 = __ldg(W2 + (2 * p + 1) * WND + n);
        __nv_bfloat16 h0 = __float2bfloat16(w0), h1 = __float2bfloat16(w1);
        float l0 = w0 - __bfloat162float(h0), l1 = w1 - __bfloat162float(h1);
        pBH[n * 20 + p] = (unsigned)__bfloat16_as_ushort(h0) | ((unsigned)__bfloat16_as_ushort(h1) << 16);
        pBL[n * 20 + p] = pkbf(l0, l1);
    }
    __syncthreads();

    const int n_chunks = (n_edges + EC - 1) / EC;
    for (int c = blockIdx.x; c < n_chunks; c += gridDim.x) {
        const int c0 = c * EC;
        // stage ef
        {
            const int lim = n_edges * HED;
            for (int l = t; l < EC * HED; l += TCB) {
                int g = c0 * HED + l;
                stage[(l >> 5) * 69 + (l & 31)] = (g < lim) ? __ldg(ef + g) : 0.f;
            }
        }
        __syncthreads();

        // MLP1 fp32 (edge t)
        float h[32];
        {
            const float* myef = stage + t * 69;
#pragma unroll
            for (int j = 0; j < 32; j++) h[j] = sB1[j];
#pragma unroll 4
            for (int i = 0; i < 32; i++) {
                float x = myef[i];
#pragma unroll
                for (int j4 = 0; j4 < 8; j4++) {
                    float4 r = *reinterpret_cast<const float4*>(sW1 + i * 32 + 4 * j4);
                    h[4 * j4 + 0] = fmaf(x, r.x, h[4 * j4 + 0]);
                    h[4 * j4 + 1] = fmaf(x, r.y, h[4 * j4 + 1]);
                    h[4 * j4 + 2] = fmaf(x, r.z, h[4 * j4 + 2]);
                    h[4 * j4 + 3] = fmaf(x, r.w, h[4 * j4 + 3]);
                }
            }
#pragma unroll
            for (int j = 0; j < 32; j++) h[j] = fmaxf(h[j], 0.f);
        }
        // write A pairs hi/lo (row t)
#pragma unroll
        for (int p = 0; p < 16; p++) {
            float x = h[2 * p], y = h[2 * p + 1];
            __nv_bfloat16 hx = __float2bfloat16(x), hy = __float2bfloat16(y);
            pAH[t * 20 + p] = (unsigned)__bfloat16_as_ushort(hx) | ((unsigned)__bfloat16_as_ushort(hy) << 16);
            pAL[t * 20 + p] = pkbf(x - __bfloat162float(hx), y - __bfloat162float(hy));
        }

        // edge meta + atom features + scalar coefs into stage row t
        const int e = c0 + t;
        const bool valid = e < n_edges;
        int src = 0;
        float shs = 0.f, s0 = 0.f, s1 = 0.f, s2 = 0.f;
        float* stw = stage + t * 69;
        if (valid) {
            int dst = __ldg(ei + e);
            src = __ldg(ei + n_edges + e);
            float4 s4 = __ldg(reinterpret_cast<const float4*>(sh) + e);
            shs = s4.x; s0 = s4.y; s1 = s4.z; s2 = s4.w;
            const float4* ar = reinterpret_cast<const float4*>(atom + dst * DD);
#pragma unroll
            for (int i = 0; i < 10; i++) {
                float4 v = __ldg(ar + i);
                stw[4 * i] = v.x; stw[4 * i + 1] = v.y; stw[4 * i + 2] = v.z; stw[4 * i + 3] = v.w;
            }
        }
        const float* st = stw;
#pragma unroll
        for (int i = 0; i < 16; i++) stw[40 + i] = st[i] * shs;
#pragma unroll
        for (int i = 0; i < 8; i++) {
            const float* xv = st + 16 + 3 * i;
            stw[56 + i] = kC110 * (xv[0] * s0 + xv[1] * s1 + xv[2] * s2);
        }
        __syncthreads();   // pA visible to all warps

        float os[16], ov[24];
#pragma unroll
        for (int o = 0; o < 16; o++) os[o] = 0.f;
#pragma unroll
        for (int o = 0; o < 24; o++) ov[o] = 0.f;

        for (int tile = 0; tile < 5; tile++) {
            // ---- mma: warp w covers cols [w*32, w*32+32) of this 128-col supertile
            for (int mt = 0; mt < 8; mt++) {
                const int r0 = mt * 16 + grp;
                unsigned ah0 = pAH[r0 * 20 + lp],       ah1 = pAH[(r0 + 8) * 20 + lp];
                unsigned ah2 = pAH[r0 * 20 + lp + 4],   ah3 = pAH[(r0 + 8) * 20 + lp + 4];
                unsigned ah4 = pAH[r0 * 20 + lp + 8],   ah5 = pAH[(r0 + 8) * 20 + lp + 8];
                unsigned ah6 = pAH[r0 * 20 + lp + 12],  ah7 = pAH[(r0 + 8) * 20 + lp + 12];
                unsigned al0 = pAL[r0 * 20 + lp],       al1 = pAL[(r0 + 8) * 20 + lp];
                unsigned al2 = pAL[r0 * 20 + lp + 4],   al3 = pAL[(r0 + 8) * 20 + lp + 4];
                unsigned al4 = pAL[r0 * 20 + lp + 8],   al5 = pAL[(r0 + 8) * 20 + lp + 8];
                unsigned al6 = pAL[r0 * 20 + lp + 12],  al7 = pAL[(r0 + 8) * 20 + lp + 12];
                for (int nn = 0; nn < 4; nn++) {
                    int n = tile * 128 + w * 32 + nn * 8 + grp;
                    unsigned bh0 = pBH[n * 20 + lp],     bh1 = pBH[n * 20 + lp + 4];
                    unsigned bh2 = pBH[n * 20 + lp + 8], bh3 = pBH[n * 20 + lp + 12];
                    unsigned bl0 = pBL[n * 20 + lp],     bl1 = pBL[n * 20 + lp + 4];
                    unsigned bl2 = pBL[n * 20 + lp + 8], bl3 = pBL[n * 20 + lp + 12];
                    float d0 = 0.f, d1 = 0.f, d2 = 0.f, d3 = 0.f;
                    mma16816(d0, d1, d2, d3, ah0, ah1, ah2, ah3, bh0, bh1);
                    mma16816(d0, d1, d2, d3, ah4, ah5, ah6, ah7, bh2, bh3);
                    mma16816(d0, d1, d2, d3, ah0, ah1, ah2, ah3, bl0, bl1);
                    mma16816(d0, d1, d2, d3, ah4, ah5, ah6, ah7, bl2, bl3);
                    mma16816(d0, d1, d2, d3, al0, al1, al2, al3, bh0, bh1);
                    mma16816(d0, d1, d2, d3, al4, al5, al6, al7, bh2, bh3);
                    int col = w * 32 + nn * 8 + lp * 2;
                    float* r0p = Dsm + r0 * 129 + col;
                    float* r1p = Dsm + (r0 + 8) * 129 + col;
                    r0p[0] = d0; r0p[1] = d1;
                    r1p[0] = d2; r1p[1] = d3;
                }
            }
            __syncthreads();

            // ---- epilogue: thread t consumes row t of D
            const float* myD = Dsm + t * 129;
            if (tile < 3) {
                for (int ib = 0; ib < 8; ib++) {
                    float aa = st[40 + tile * 8 + ib];
#pragma unroll
                    for (int o = 0; o < 16; o++) {
                        int n = tile * 128 + ib * 16 + o;
                        os[o] = fmaf(myD[ib * 16 + o] + sB2[n], aa, os[o]);
                    }
                }
            } else {
                for (int ii = 0; ii < 16; ii++) {
                    int i3 = (tile - 3) * 16 + ii;
                    float m0, m1, m2;
                    if (i3 < 16) {
                        float x = st[i3];
                        m0 = x * s0; m1 = x * s1; m2 = x * s2;
                    } else if (i3 < 24) {
                        const float* xv = st + 16 + 3 * (i3 - 16);
                        m0 = xv[0] * shs; m1 = xv[1] * shs; m2 = xv[2] * shs;
                    } else {
                        const float* xv = st + 16 + 3 * (i3 - 24);
                        m0 = kC111 * (xv[1] * s2 - xv[2] * s1);
                        m1 = kC111 * (xv[2] * s0 - xv[0] * s2);
                        m2 = kC111 * (xv[0] * s1 - xv[1] * s0);
                    }
#pragma unroll
                    for (int oo = 0; oo < 8; oo++) {
                        int n = 384 + i3 * 8 + oo;
                        float wv = myD[ii * 8 + oo] + sB2[n];
                        ov[3 * oo + 0] = fmaf(wv, m0, ov[3 * oo + 0]);
                        ov[3 * oo + 1] = fmaf(wv, m1, ov[3 * oo + 1]);
                        ov[3 * oo + 2] = fmaf(wv, m2, ov[3 * oo + 2]);
                    }
                }
            }
            __syncthreads();
        }

        if (valid) {
            if (IS_K) {
                const float* q = d_qnode + src * DD;
                float attn = 0.f;
#pragma unroll
                for (int o = 0; o < 16; o++) attn = fmaf(os[o], __ldg(q + o), attn);
#pragma unroll
                for (int cc = 0; cc < 24; cc++) attn = fmaf(ov[cc], __ldg(q + 16 + cc), attn);
                d_attn[e] = attn;
                atomicMax(&d_nmax[src], encf(attn));
            } else {
#pragma unroll
                for (int o = 0; o < 16; o++) d_vedge[o * n_edges + e] = os[o];
#pragma unroll
                for (int cc = 0; cc < 24; cc++) d_vedge[(16 + cc) * n_edges + e] = ov[cc];
            }
        }
    }
}

__global__ void k_soft(const int* __restrict__ ei, int n_edges) {
    int e = blockIdx.x * blockDim.x + threadIdx.x;
    if (e >= n_edges) return;
    int src = __ldg(ei + n_edges + e);
    float m = decf(d_nmax[src]);
    float a = expf(d_attn[e] - m);
    atomicAdd(&d_denom[src], a);
    float* u = d_upd + src * DD;
#pragma unroll
    for (int c = 0; c < DD; c++)
        atomicAdd(u + c, a * d_vedge[c * n_edges + e]);
}

__global__ void k_stats(const float* __restrict__ atom, int n_nodes) {
    __shared__ float red[40];
    int t = threadIdx.x;
    if (t < 40) red[t] = 0.f;
    __syncthreads();
    int n = blockIdx.x * blockDim.x + t;
    float y[40];
    if (n < n_nodes) {
        float den = d_denom[n];
        float inv = den > 0.f ? 1.f / den : 0.f;
#pragma unroll
        for (int c = 0; c < 40; c++) {
            y[c] = atom[n * DD + c] + d_upd[n * DD + c] * inv;
            d_ybuf[n * DD + c] = y[c];
        }
    } else {
#pragma unroll
        for (int c = 0; c < 40; c++) y[c] = 0.f;
    }
    const unsigned full = 0xffffffffu;
#pragma unroll
    for (int c = 0; c < 16; c++) {
        float v = y[c], v2 = v * v;
#pragma unroll
        for (int o = 16; o > 0; o >>= 1) {
            v  += __shfl_down_sync(full, v, o);
            v2 += __shfl_down_sync(full, v2, o);
        }
        if ((t & 31) == 0) { atomicAdd(&red[c], v); atomicAdd(&red[16 + c], v2); }
    }
#pragma unroll
    for (int i = 0; i < 8; i++) {
        float v = y[16 + 3 * i] * y[16 + 3 * i] + y[17 + 3 * i] * y[17 + 3 * i]
                + y[18 + 3 * i] * y[18 + 3 * i];
#pragma unroll
        for (int o = 16; o > 0; o >>= 1) v += __shfl_down_sync(full, v, o);
        if ((t & 31) == 0) atomicAdd(&red[32 + i], v);
    }
    __syncthreads();
    if (t < 40) atomicAdd(&d_gstats[t], red[t]);
}

__global__ void k_bn(const float* __restrict__ ws, const float* __restrict__ bs,
                     const float* __restrict__ wv, int n_nodes) {
    int t = threadIdx.x;
    float N = (float)n_nodes;
    if (t < 16) {
        float mu  = d_gstats[t] / N;
        float var = d_gstats[16 + t] / N - mu * mu;
        float A = __ldg(ws + t) / sqrtf(var + EPSV);
        d_bnp[t] = A;
        d_bnp[16 + t] = __ldg(bs + t) - mu * A;
    } else if (t < 24) {
        int i = t - 16;
        float norm = d_gstats[32 + i] / (3.f * N);
        d_bnp[32 + i] = __ldg(wv + i) / sqrtf(norm + EPSV);
    }
}

__global__ void k_out(float* __restrict__ out, int n_nodes) {
    int idx = blockIdx.x * blockDim.x + threadIdx.x;
    if (idx >= n_nodes * DD) return;
    int c = idx % DD;
    float y = d_ybuf[idx];
    out[idx] = (c < 16) ? (y * d_bnp[c] + d_bnp[16 + c])
                        : (y * d_bnp[32 + (c - 16) / 3]);
}

__global__ void k_copy(const float* __restrict__ src, float* __restrict__ dst, int n4) {
    int i = blockIdx.x * blockDim.x + threadIdx.x;
    if (i < n4)
        reinterpret_cast<float4*>(dst)[i] = __ldg(reinterpret_cast<const float4*>(src) + i);
}

extern "C" void kernel_launch(void* const* d_in, const int* in_sizes, int n_in,
                              void* d_out, int out_size) {
    const float* atom = (const float*)d_in[0];
    const float* ef   = (const float*)d_in[1];
    const float* sh   = (const float*)d_in[2];
    const float* Wqs  = (const float*)d_in[3];
    const float* Wqv  = (const float*)d_in[4];
    const float* kw1  = (const float*)d_in[5];
    const float* kb1  = (const float*)d_in[6];
    const float* kw2  = (const float*)d_in[7];
    const float* kb2  = (const float*)d_in[8];
    const float* vw1  = (const float*)d_in[9];
    const float* vb1  = (const float*)d_in[10];
    const float* vw2  = (const float*)d_in[11];
    const float* vb2  = (const float*)d_in[12];
    const float* bnws = (const float*)d_in[13];
    const float* bnbs = (const float*)d_in[14];
    const float* bnwv = (const float*)d_in[15];
    const int*   ei   = (const int*)d_in[16];

    int n_nodes = in_sizes[0] / DD;
    int n_edges = in_sizes[1] / HED;
    float* out = (float*)d_out;

    cudaFuncSetAttribute(k_edge_mma<true>,  cudaFuncAttributeMaxDynamicSharedMemorySize, SM_TC);
    cudaFuncSetAttribute(k_edge_mma<false>, cudaFuncAttributeMaxDynamicSharedMemorySize, SM_TC);

    k_init<<<(n_nodes * DD + 255) / 256, 256>>>(n_nodes);
    k_qnode<<<(n_nodes + 255) / 256, 256>>>(atom, Wqs, Wqv, n_nodes);

    k_edge_mma<true><<<148, TCB, SM_TC>>>(atom, ef, sh, ei, kw1, kb1, kw2, kb2, n_edges);
    k_edge_mma<false><<<148, TCB, SM_TC>>>(atom, ef, sh, ei, vw1, vb1, vw2, vb2, n_edges);

    k_soft<<<(n_edges + 255) / 256, 256>>>(ei, n_edges);
    k_stats<<<(n_nodes + 255) / 256, 256>>>(atom, n_nodes);
    k_bn<<<1, 64>>>(bnws, bnbs, bnwv, n_nodes);
    k_out<<<(n_nodes * DD + 255) / 256, 256>>>(out, n_nodes);

    int n4 = (n_edges * HED) / 4;
    k_copy<<<(n4 + 255) / 256, 256>>>(ef, out + n_nodes * DD, n4);
}

// round 12
// speedup vs baseline: 1.4867x; 1.4867x over previous
#include <cuda_runtime.h>
#include <cuda_bf16.h>

#define NSD 16
#define NVD 8
#define HED 32
#define DD  40
#define WND 640
#define MAXN 10000
#define MAXE 160000
#define EPSV 1e-5f
#define EC   128
#define TCB  256

// smem float offsets
#define OFF_W1  0
#define OFF_B1  1024
#define OFF_B2  1056
#define OFF_STG 1696            // stage: 128 rows x 69 (atom 0..39, coef 40..63, sh 64..67)
#define OFF_PAH 10528           // A pairs hi: 128 x 20 u32
#define OFF_PAL 13088
#define OFF_PBH 15648           // B pairs hi: 640 x 20 u32
#define OFF_PBL 28448
#define OFF_DSM 41248           // D tile: 128 x 129 f32 (also merge buffer)
#define SM_FLT  57760
#define SM_TC   (SM_FLT * 4)

__device__ __constant__ float kC110 = 0.57735026918962576f;
__device__ __constant__ float kC111 = 0.70710678118654752f;

__device__ float    d_qnode[MAXN * DD];
__device__ float    d_attn [MAXE];
__device__ float    d_vedge[MAXE * DD];
__device__ unsigned d_nmax [MAXN];
__device__ float    d_denom[MAXN];
__device__ float    d_upd  [MAXN * DD];
__device__ float    d_ybuf [MAXN * DD];
__device__ float    d_gstats[48];
__device__ float    d_bnp  [48];

__device__ __forceinline__ unsigned encf(float f) {
    unsigned u = __float_as_uint(f);
    return (u & 0x80000000u) ? ~u : (u | 0x80000000u);
}
__device__ __forceinline__ float decf(unsigned u) {
    return (u & 0x80000000u) ? __uint_as_float(u ^ 0x80000000u) : __uint_as_float(~u);
}

__device__ __forceinline__ void mma16816(float& d0, float& d1, float& d2, float& d3,
                                         unsigned a0, unsigned a1, unsigned a2, unsigned a3,
                                         unsigned b0, unsigned b1) {
    asm volatile(
        "mma.sync.aligned.m16n8k16.row.col.f32.bf16.bf16.f32 "
        "{%0,%1,%2,%3}, {%4,%5,%6,%7}, {%8,%9}, {%0,%1,%2,%3};"
        : "+f"(d0), "+f"(d1), "+f"(d2), "+f"(d3)
        : "r"(a0), "r"(a1), "r"(a2), "r"(a3), "r"(b0), "r"(b1));
}
__device__ __forceinline__ unsigned pkbf(float x, float y) {
    __nv_bfloat16 bx = __float2bfloat16(x), by = __float2bfloat16(y);
    return (unsigned)__bfloat16_as_ushort(bx) | ((unsigned)__bfloat16_as_ushort(by) << 16);
}

__global__ void k_init(int n_nodes) {
    int i = blockIdx.x * blockDim.x + threadIdx.x;
    if (i < n_nodes * DD) d_upd[i] = 0.f;
    if (i < n_nodes) { d_denom[i] = 0.f; d_nmax[i] = 0u; }
    if (i < 48) d_gstats[i] = 0.f;
}

__global__ void k_qnode(const float* __restrict__ atom, const float* __restrict__ Wqs,
                        const float* __restrict__ Wqv, int n_nodes) {
    int n = blockIdx.x * blockDim.x + threadIdx.x;
    if (n >= n_nodes) return;
    const float* a = atom + n * DD;
    float qs[16], qv[24];
#pragma unroll
    for (int o = 0; o < 16; o++) qs[o] = 0.f;
#pragma unroll
    for (int c = 0; c < 24; c++) qv[c] = 0.f;
    for (int i = 0; i < 16; i++) {
        float x = __ldg(a + i);
#pragma unroll
        for (int o = 0; o < 16; o++) qs[o] = fmaf(x, __ldg(Wqs + i * 16 + o), qs[o]);
    }
    for (int i = 0; i < 8; i++) {
        float x0 = __ldg(a + 16 + 3 * i), x1 = __ldg(a + 17 + 3 * i), x2 = __ldg(a + 18 + 3 * i);
#pragma unroll
        for (int o = 0; o < 8; o++) {
            float w = __ldg(Wqv + i * 8 + o);
            qv[3 * o + 0] = fmaf(w, x0, qv[3 * o + 0]);
            qv[3 * o + 1] = fmaf(w, x1, qv[3 * o + 1]);
            qv[3 * o + 2] = fmaf(w, x2, qv[3 * o + 2]);
        }
    }
    float* q = d_qnode + n * DD;
#pragma unroll
    for (int o = 0; o < 16; o++) q[o] = qs[o];
#pragma unroll
    for (int c = 0; c < 24; c++) q[16 + c] = qv[c];
}

template <bool IS_K>
__global__ void __launch_bounds__(TCB, 1) k_edge_mma(
    const float* __restrict__ atom, const float* __restrict__ ef,
    const float* __restrict__ sh, const int* __restrict__ ei,
    const float* __restrict__ W1, const float* __restrict__ B1,
    const float* __restrict__ W2, const float* __restrict__ B2,
    int n_edges)
{
    extern __shared__ float sm[];
    float* sW1 = sm + OFF_W1;
    float* sB1 = sm + OFF_B1;
    float* sB2 = sm + OFF_B2;
    float* stage = sm + OFF_STG;
    unsigned* pAH = (unsigned*)(sm + OFF_PAH);
    unsigned* pAL = (unsigned*)(sm + OFF_PAL);
    unsigned* pBH = (unsigned*)(sm + OFF_PBH);
    unsigned* pBL = (unsigned*)(sm + OFF_PBL);
    float* Dsm = sm + OFF_DSM;

    const int t = threadIdx.x;
    const int w = t >> 5, lane = t & 31;
    const int grp = lane >> 2, lp = lane & 3;
    const int er = t & 127;     // edge row (MLP / epilogue)
    const int hf = t >> 7;      // half index (0/1)

    for (int i = t; i < 1024; i += TCB) sW1[i] = __ldg(W1 + i);
    if (t < 32) sB1[t] = __ldg(B1 + t);
    for (int i = t; i < WND; i += TCB) sB2[i] = __ldg(B2 + i);
    // W2 [32][640] -> k-pair-packed bf16 hi/lo: pB[n][p] = (W2[2p][n], W2[2p+1][n])
    for (int idx = t; idx < WND * 16; idx += TCB) {
        int n = idx >> 4, p = idx & 15;
        float w0 = __ldg(W2 + (2 * p) * WND + n);
        float w1 = __ldg(W2 + (2 * p + 1) * WND + n);
        __nv_bfloat16 h0 = __float2bfloat16(w0), h1 = __float2bfloat16(w1);
        float l0 = w0 - __bfloat162float(h0), l1 = w1 - __bfloat162float(h1);
        pBH[n * 20 + p] = (unsigned)__bfloat16_as_ushort(h0) | ((unsigned)__bfloat16_as_ushort(h1) << 16);
        pBL[n * 20 + p] = pkbf(l0, l1);
    }
    __syncthreads();

    const int n_chunks = (n_edges + EC - 1) / EC;
    for (int c = blockIdx.x; c < n_chunks; c += gridDim.x) {
        const int c0 = c * EC;
        // stage ef
        {
            const int lim = n_edges * HED;
            for (int l = t; l < EC * HED; l += TCB) {
                int g = c0 * HED + l;
                stage[(l >> 5) * 69 + (l & 31)] = (g < lim) ? __ldg(ef + g) : 0.f;
            }
        }
        __syncthreads();

        // MLP1: thread computes h[hf*16 .. hf*16+16) for edge er
        {
            float hreg[16];
            const float* myef = stage + er * 69;
            const float* b1h = sB1 + hf * 16;
#pragma unroll
            for (int j = 0; j < 16; j++) hreg[j] = b1h[j];
#pragma unroll 4
            for (int i = 0; i < 32; i++) {
                float x = myef[i];
#pragma unroll
                for (int j4 = 0; j4 < 4; j4++) {
                    float4 r = *reinterpret_cast<const float4*>(sW1 + i * 32 + hf * 16 + 4 * j4);
                    hreg[4 * j4 + 0] = fmaf(x, r.x, hreg[4 * j4 + 0]);
                    hreg[4 * j4 + 1] = fmaf(x, r.y, hreg[4 * j4 + 1]);
                    hreg[4 * j4 + 2] = fmaf(x, r.z, hreg[4 * j4 + 2]);
                    hreg[4 * j4 + 3] = fmaf(x, r.w, hreg[4 * j4 + 3]);
                }
            }
#pragma unroll
            for (int j = 0; j < 16; j++) hreg[j] = fmaxf(hreg[j], 0.f);
            // pA pairs p = hf*8 + [0..8)
#pragma unroll
            for (int p = 0; p < 8; p++) {
                float x = hreg[2 * p], y = hreg[2 * p + 1];
                __nv_bfloat16 hx = __float2bfloat16(x), hy = __float2bfloat16(y);
                pAH[er * 20 + hf * 8 + p] =
                    (unsigned)__bfloat16_as_ushort(hx) | ((unsigned)__bfloat16_as_ushort(hy) << 16);
                pAL[er * 20 + hf * 8 + p] = pkbf(x - __bfloat162float(hx), y - __bfloat162float(hy));
            }
        }
        __syncthreads();   // all ef reads done; pA complete

        // phase C: half 0 writes atom features, scalar coefs, sh into stage row er
        const int e = c0 + er;
        const bool valid = e < n_edges;
        int src = 0;
        if (hf == 0) {
            float shs = 0.f, s0 = 0.f, s1 = 0.f, s2 = 0.f;
            float* stw = stage + er * 69;
            if (valid) {
                int dst = __ldg(ei + e);
                src = __ldg(ei + n_edges + e);
                float4 s4 = __ldg(reinterpret_cast<const float4*>(sh) + e);
                shs = s4.x; s0 = s4.y; s1 = s4.z; s2 = s4.w;
                const float4* ar = reinterpret_cast<const float4*>(atom + dst * DD);
#pragma unroll
                for (int i = 0; i < 10; i++) {
                    float4 v = __ldg(ar + i);
                    stw[4 * i] = v.x; stw[4 * i + 1] = v.y;
                    stw[4 * i + 2] = v.z; stw[4 * i + 3] = v.w;
                }
            } else {
#pragma unroll
                for (int i = 0; i < 40; i++) stw[i] = 0.f;
            }
            stw[64] = shs; stw[65] = s0; stw[66] = s1; stw[67] = s2;
#pragma unroll
            for (int i = 0; i < 16; i++) stw[40 + i] = stw[i] * shs;
#pragma unroll
            for (int i = 0; i < 8; i++) {
                const float* xv = stw + 16 + 3 * i;
                stw[56 + i] = kC110 * (xv[0] * s0 + xv[1] * s1 + xv[2] * s2);
            }
        }
        __syncthreads();

        const float* st = stage + er * 69;
        float os[16], ov[24];
#pragma unroll
        for (int o = 0; o < 16; o++) os[o] = 0.f;
#pragma unroll
        for (int o = 0; o < 24; o++) ov[o] = 0.f;

        for (int tile = 0; tile < 5; tile++) {
            // ---- mma: warp w covers cols [w*16, w*16+16) of the 128-col supertile
            unsigned bh[2][4], bl[2][4];
#pragma unroll
            for (int nn = 0; nn < 2; nn++) {
                int n = tile * 128 + w * 16 + nn * 8 + grp;
#pragma unroll
                for (int k = 0; k < 4; k++) {
                    bh[nn][k] = pBH[n * 20 + lp + 4 * k];
                    bl[nn][k] = pBL[n * 20 + lp + 4 * k];
                }
            }
            for (int mt = 0; mt < 8; mt++) {
                const int r0 = mt * 16 + grp;
                unsigned ah0 = pAH[r0 * 20 + lp],       ah1 = pAH[(r0 + 8) * 20 + lp];
                unsigned ah2 = pAH[r0 * 20 + lp + 4],   ah3 = pAH[(r0 + 8) * 20 + lp + 4];
                unsigned ah4 = pAH[r0 * 20 + lp + 8],   ah5 = pAH[(r0 + 8) * 20 + lp + 8];
                unsigned ah6 = pAH[r0 * 20 + lp + 12],  ah7 = pAH[(r0 + 8) * 20 + lp + 12];
                unsigned al0 = pAL[r0 * 20 + lp],       al1 = pAL[(r0 + 8) * 20 + lp];
                unsigned al2 = pAL[r0 * 20 + lp + 4],   al3 = pAL[(r0 + 8) * 20 + lp + 4];
                unsigned al4 = pAL[r0 * 20 + lp + 8],   al5 = pAL[(r0 + 8) * 20 + lp + 8];
                unsigned al6 = pAL[r0 * 20 + lp + 12],  al7 = pAL[(r0 + 8) * 20 + lp + 12];
#pragma unroll
                for (int nn = 0; nn < 2; nn++) {
                    float a0 = 0.f, a1 = 0.f, a2 = 0.f, a3 = 0.f;   // chain A
                    float b0 = 0.f, b1 = 0.f, b2 = 0.f, b3 = 0.f;   // chain B
                    mma16816(a0, a1, a2, a3, ah0, ah1, ah2, ah3, bh[nn][0], bh[nn][1]);
                    mma16816(a0, a1, a2, a3, ah4, ah5, ah6, ah7, bh[nn][2], bh[nn][3]);
                    mma16816(a0, a1, a2, a3, ah0, ah1, ah2, ah3, bl[nn][0], bl[nn][1]);
                    mma16816(b0, b1, b2, b3, ah4, ah5, ah6, ah7, bl[nn][2], bl[nn][3]);
                    mma16816(b0, b1, b2, b3, al0, al1, al2, al3, bh[nn][0], bh[nn][1]);
                    mma16816(b0, b1, b2, b3, al4, al5, al6, al7, bh[nn][2], bh[nn][3]);
                    int col = w * 16 + nn * 8 + lp * 2;
                    float* r0p = Dsm + r0 * 129 + col;
                    float* r1p = Dsm + (r0 + 8) * 129 + col;
                    r0p[0] = a0 + b0; r0p[1] = a1 + b1;
                    r1p[0] = a2 + b2; r1p[1] = a3 + b3;
                }
            }
            __syncthreads();

            // ---- epilogue: thread (er, hf) consumes half the columns of row er
            const float* myD = Dsm + er * 129;
            if (tile < 3) {
                for (int ib = hf * 4; ib < hf * 4 + 4; ib++) {
                    float aa = st[40 + tile * 8 + ib];
#pragma unroll
                    for (int o = 0; o < 16; o++) {
                        int n = tile * 128 + ib * 16 + o;
                        os[o] = fmaf(myD[ib * 16 + o] + sB2[n], aa, os[o]);
                    }
                }
            } else {
                float shs = st[64], s0 = st[65], s1 = st[66], s2 = st[67];
                for (int ii = hf * 8; ii < hf * 8 + 8; ii++) {
                    int i3 = (tile - 3) * 16 + ii;
                    float m0, m1, m2;
                    if (i3 < 16) {
                        float x = st[i3];
                        m0 = x * s0; m1 = x * s1; m2 = x * s2;
                    } else if (i3 < 24) {
                        const float* xv = st + 16 + 3 * (i3 - 16);
                        m0 = xv[0] * shs; m1 = xv[1] * shs; m2 = xv[2] * shs;
                    } else {
                        const float* xv = st + 16 + 3 * (i3 - 24);
                        m0 = kC111 * (xv[1] * s2 - xv[2] * s1);
                        m1 = kC111 * (xv[2] * s0 - xv[0] * s2);
                        m2 = kC111 * (xv[0] * s1 - xv[1] * s0);
                    }
#pragma unroll
                    for (int oo = 0; oo < 8; oo++) {
                        int n = 384 + i3 * 8 + oo;
                        float wv = myD[ii * 8 + oo] + sB2[n];
                        ov[3 * oo + 0] = fmaf(wv, m0, ov[3 * oo + 0]);
                        ov[3 * oo + 1] = fmaf(wv, m1, ov[3 * oo + 1]);
                        ov[3 * oo + 2] = fmaf(wv, m2, ov[3 * oo + 2]);
                    }
                }
            }
            __syncthreads();
        }

        // merge halves: half 1 writes partials to Dsm, half 0 adds and emits
        if (hf == 1) {
            float* mrow = Dsm + er * 129;
#pragma unroll
            for (int o = 0; o < 16; o++) mrow[o] = os[o];
#pragma unroll
            for (int cc = 0; cc < 24; cc++) mrow[16 + cc] = ov[cc];
        }
        __syncthreads();
        if (hf == 0 && valid) {
            const float* mrow = Dsm + er * 129;
#pragma unroll
            for (int o = 0; o < 16; o++) os[o] += mrow[o];
#pragma unroll
            for (int cc = 0; cc < 24; cc++) ov[cc] += mrow[16 + cc];

            if (IS_K) {
                const float* q = d_qnode + src * DD;
                float attn = 0.f;
#pragma unroll
                for (int o = 0; o < 16; o++) attn = fmaf(os[o], __ldg(q + o), attn);
#pragma unroll
                for (int cc = 0; cc < 24; cc++) attn = fmaf(ov[cc], __ldg(q + 16 + cc), attn);
                d_attn[e] = attn;
                atomicMax(&d_nmax[src], encf(attn));
            } else {
#pragma unroll
                for (int o = 0; o < 16; o++) d_vedge[o * n_edges + e] = os[o];
#pragma unroll
                for (int cc = 0; cc < 24; cc++) d_vedge[(16 + cc) * n_edges + e] = ov[cc];
            }
        }
        __syncthreads();
    }
}

__global__ void k_soft(const int* __restrict__ ei, int n_edges) {
    int e = blockIdx.x * blockDim.x + threadIdx.x;
    if (e >= n_edges) return;
    int src = __ldg(ei + n_edges + e);
    float m = decf(d_nmax[src]);
    float a = expf(d_attn[e] - m);
    atomicAdd(&d_denom[src], a);
    float* u = d_upd + src * DD;
#pragma unroll
    for (int c = 0; c < DD; c++)
        atomicAdd(u + c, a * d_vedge[c * n_edges + e]);
}

__global__ void k_stats(const float* __restrict__ atom, int n_nodes) {
    __shared__ float red[40];
    int t = threadIdx.x;
    if (t < 40) red[t] = 0.f;
    __syncthreads();
    int n = blockIdx.x * blockDim.x + t;
    float y[40];
    if (n < n_nodes) {
        float den = d_denom[n];
        float inv = den > 0.f ? 1.f / den : 0.f;
#pragma unroll
        for (int c = 0; c < 40; c++) {
            y[c] = atom[n * DD + c] + d_upd[n * DD + c] * inv;
            d_ybuf[n * DD + c] = y[c];
        }
    } else {
#pragma unroll
        for (int c = 0; c < 40; c++) y[c] = 0.f;
    }
    const unsigned full = 0xffffffffu;
#pragma unroll
    for (int c = 0; c < 16; c++) {
        float v = y[c], v2 = v * v;
#pragma unroll
        for (int o = 16; o > 0; o >>= 1) {
            v  += __shfl_down_sync(full, v, o);
            v2 += __shfl_down_sync(full, v2, o);
        }
        if ((t & 31) == 0) { atomicAdd(&red[c], v); atomicAdd(&red[16 + c], v2); }
    }
#pragma unroll
    for (int i = 0; i < 8; i++) {
        float v = y[16 + 3 * i] * y[16 + 3 * i] + y[17 + 3 * i] * y[17 + 3 * i]
                + y[18 + 3 * i] * y[18 + 3 * i];
#pragma unroll
        for (int o = 16; o > 0; o >>= 1) v += __shfl_down_sync(full, v, o);
        if ((t & 31) == 0) atomicAdd(&red[32 + i], v);
    }
    __syncthreads();
    if (t < 40) atomicAdd(&d_gstats[t], red[t]);
}

__global__ void k_bn(const float* __restrict__ ws, const float* __restrict__ bs,
                     const float* __restrict__ wv, int n_nodes) {
    int t = threadIdx.x;
    float N = (float)n_nodes;
    if (t < 16) {
        float mu  = d_gstats[t] / N;
        float var = d_gstats[16 + t] / N - mu * mu;
        float A = __ldg(ws + t) / sqrtf(var + EPSV);
        d_bnp[t] = A;
        d_bnp[16 + t] = __ldg(bs + t) - mu * A;
    } else if (t < 24) {
        int i = t - 16;
        float norm = d_gstats[32 + i] / (3.f * N);
        d_bnp[32 + i] = __ldg(wv + i) / sqrtf(norm + EPSV);
    }
}

__global__ void k_out(float* __restrict__ out, int n_nodes) {
    int idx = blockIdx.x * blockDim.x + threadIdx.x;
    if (idx >= n_nodes * DD) return;
    int c = idx % DD;
    float y = d_ybuf[idx];
    out[idx] = (c < 16) ? (y * d_bnp[c] + d_bnp[16 + c])
                        : (y * d_bnp[32 + (c - 16) / 3]);
}

__global__ void k_copy(const float* __restrict__ src, float* __restrict__ dst, int n4) {
    int i = blockIdx.x * blockDim.x + threadIdx.x;
    if (i < n4)
        reinterpret_cast<float4*>(dst)[i] = __ldg(reinterpret_cast<const float4*>(src) + i);
}

extern "C" void kernel_launch(void* const* d_in, const int* in_sizes, int n_in,
                              void* d_out, int out_size) {
    const float* atom = (const float*)d_in[0];
    const float* ef   = (const float*)d_in[1];
    const float* sh   = (const float*)d_in[2];
    const float* Wqs  = (const float*)d_in[3];
    const float* Wqv  = (const float*)d_in[4];
    const float* kw1  = (const float*)d_in[5];
    const float* kb1  = (const float*)d_in[6];
    const float* kw2  = (const float*)d_in[7];
    const float* kb2  = (const float*)d_in[8];
    const float* vw1  = (const float*)d_in[9];
    const float* vb1  = (const float*)d_in[10];
    const float* vw2  = (const float*)d_in[11];
    const float* vb2  = (const float*)d_in[12];
    const float* bnws = (const float*)d_in[13];
    const float* bnbs = (const float*)d_in[14];
    const float* bnwv = (const float*)d_in[15];
    const int*   ei   = (const int*)d_in[16];

    int n_nodes = in_sizes[0] / DD;
    int n_edges = in_sizes[1] / HED;
    float* out = (float*)d_out;

    cudaFuncSetAttribute(k_edge_mma<true>,  cudaFuncAttributeMaxDynamicSharedMemorySize, SM_TC);
    cudaFuncSetAttribute(k_edge_mma<false>, cudaFuncAttributeMaxDynamicSharedMemorySize, SM_TC);

    k_init<<<(n_nodes * DD + 255) / 256, 256>>>(n_nodes);
    k_qnode<<<(n_nodes + 255) / 256, 256>>>(atom, Wqs, Wqv, n_nodes);

    k_edge_mma<true><<<148, TCB, SM_TC>>>(atom, ef, sh, ei, kw1, kb1, kw2, kb2, n_edges);
    k_edge_mma<false><<<148, TCB, SM_TC>>>(atom, ef, sh, ei, vw1, vb1, vw2, vb2, n_edges);

    k_soft<<<(n_edges + 255) / 256, 256>>>(ei, n_edges);
    k_stats<<<(n_nodes + 255) / 256, 256>>>(atom, n_nodes);
    k_bn<<<1, 64>>>(bnws, bnbs, bnwv, n_nodes);
    k_out<<<(n_nodes * DD + 255) / 256, 256>>>(out, n_nodes);

    int n4 = (n_edges * HED) / 4;
    k_copy<<<(n4 + 255) / 256, 256>>>(ef, out + n_nodes * DD, n4);
}

// round 13
// speedup vs baseline: 1.5278x; 1.0276x over previous
#include <cuda_runtime.h>
#include <cuda_bf16.h>

#define NSD 16
#define NVD 8
#define HED 32
#define DD  40
#define WND 640
#define MAXN 10000
#define MAXE 160000
#define EPSV 1e-5f
#define EC   128
#define TCB  256

// smem float offsets
#define OFF_W1  0
#define OFF_B1  1024
#define OFF_B2  1056
#define OFF_STG 1696            // stage: 128 rows x 69 (atom 0..39, coef 40..63, sh 64..67)
#define OFF_PAH 10528           // A pairs hi: 128 x 20 u32
#define OFF_PAL 13088
#define OFF_PBH 15648           // B pairs hi: 640 x 20 u32
#define OFF_PBL 28448
#define OFF_DSM 41248           // D tile: 128 x 129 f32 (also merge buffer)
#define SM_FLT  57760
#define SM_TC   (SM_FLT * 4)

__device__ __constant__ float kC110 = 0.57735026918962576f;
__device__ __constant__ float kC111 = 0.70710678118654752f;

__device__ float    d_qnode[MAXN * DD];
__device__ float    d_attn [MAXE];
__device__ float    d_vedge[MAXE * DD];
__device__ unsigned d_nmax [MAXN];
__device__ float    d_denom[MAXN];
__device__ float    d_upd  [MAXN * DD];
__device__ float    d_ybuf [MAXN * DD];
__device__ float    d_gstats[48];
__device__ float    d_bnp  [48];

__device__ __forceinline__ unsigned encf(float f) {
    unsigned u = __float_as_uint(f);
    return (u & 0x80000000u) ? ~u : (u | 0x80000000u);
}
__device__ __forceinline__ float decf(unsigned u) {
    return (u & 0x80000000u) ? __uint_as_float(u ^ 0x80000000u) : __uint_as_float(~u);
}
__device__ __forceinline__ unsigned s2u(const void* p) {
    unsigned a;
    asm("{ .reg .u64 t; cvta.to.shared.u64 t, %1; cvt.u32.u64 %0, t; }" : "=r"(a) : "l"(p));
    return a;
}

__device__ __forceinline__ void mma16816(float& d0, float& d1, float& d2, float& d3,
                                         unsigned a0, unsigned a1, unsigned a2, unsigned a3,
                                         unsigned b0, unsigned b1) {
    asm volatile(
        "mma.sync.aligned.m16n8k16.row.col.f32.bf16.bf16.f32 "
        "{%0,%1,%2,%3}, {%4,%5,%6,%7}, {%8,%9}, {%0,%1,%2,%3};"
        : "+f"(d0), "+f"(d1), "+f"(d2), "+f"(d3)
        : "r"(a0), "r"(a1), "r"(a2), "r"(a3), "r"(b0), "r"(b1));
}
__device__ __forceinline__ void ldm4(unsigned& r0, unsigned& r1, unsigned& r2, unsigned& r3,
                                     unsigned addr) {
    asm volatile("ldmatrix.sync.aligned.m8n8.x4.shared.b16 {%0,%1,%2,%3}, [%4];"
                 : "=r"(r0), "=r"(r1), "=r"(r2), "=r"(r3) : "r"(addr));
}
__device__ __forceinline__ unsigned pkbf(float x, float y) {
    __nv_bfloat16 bx = __float2bfloat16(x), by = __float2bfloat16(y);
    return (unsigned)__bfloat16_as_ushort(bx) | ((unsigned)__bfloat16_as_ushort(by) << 16);
}

__global__ void k_init(int n_nodes) {
    int i = blockIdx.x * blockDim.x + threadIdx.x;
    if (i < n_nodes * DD) d_upd[i] = 0.f;
    if (i < n_nodes) { d_denom[i] = 0.f; d_nmax[i] = 0u; }
    if (i < 48) d_gstats[i] = 0.f;
}

__global__ void k_qnode(const float* __restrict__ atom, const float* __restrict__ Wqs,
                        const float* __restrict__ Wqv, int n_nodes) {
    int n = blockIdx.x * blockDim.x + threadIdx.x;
    if (n >= n_nodes) return;
    const float* a = atom + n * DD;
    float qs[16], qv[24];
#pragma unroll
    for (int o = 0; o < 16; o++) qs[o] = 0.f;
#pragma unroll
    for (int c = 0; c < 24; c++) qv[c] = 0.f;
    for (int i = 0; i < 16; i++) {
        float x = __ldg(a + i);
#pragma unroll
        for (int o = 0; o < 16; o++) qs[o] = fmaf(x, __ldg(Wqs + i * 16 + o), qs[o]);
    }
    for (int i = 0; i < 8; i++) {
        float x0 = __ldg(a + 16 + 3 * i), x1 = __ldg(a + 17 + 3 * i), x2 = __ldg(a + 18 + 3 * i);
#pragma unroll
        for (int o = 0; o < 8; o++) {
            float w = __ldg(Wqv + i * 8 + o);
            qv[3 * o + 0] = fmaf(w, x0, qv[3 * o + 0]);
            qv[3 * o + 1] = fmaf(w, x1, qv[3 * o + 1]);
            qv[3 * o + 2] = fmaf(w, x2, qv[3 * o + 2]);
        }
    }
    float* q = d_qnode + n * DD;
#pragma unroll
    for (int o = 0; o < 16; o++) q[o] = qs[o];
#pragma unroll
    for (int c = 0; c < 24; c++) q[16 + c] = qv[c];
}

template <bool IS_K>
__global__ void __launch_bounds__(TCB, 1) k_edge_mma(
    const float* __restrict__ atom, const float* __restrict__ ef,
    const float* __restrict__ sh, const int* __restrict__ ei,
    const float* __restrict__ W1, const float* __restrict__ B1,
    const float* __restrict__ W2, const float* __restrict__ B2,
    int n_edges)
{
    extern __shared__ float sm[];
    float* sW1 = sm + OFF_W1;
    float* sB1 = sm + OFF_B1;
    float* sB2 = sm + OFF_B2;
    float* stage = sm + OFF_STG;
    unsigned* pAH = (unsigned*)(sm + OFF_PAH);
    unsigned* pAL = (unsigned*)(sm + OFF_PAL);
    unsigned* pBH = (unsigned*)(sm + OFF_PBH);
    unsigned* pBL = (unsigned*)(sm + OFF_PBL);
    float* Dsm = sm + OFF_DSM;

    const int t = threadIdx.x;
    const int w = t >> 5, lane = t & 31;
    const int er = t & 127;     // edge row (MLP / epilogue)
    const int hf = t >> 7;      // half index (0/1)

    for (int i = t; i < 1024; i += TCB) sW1[i] = __ldg(W1 + i);
    if (t < 32) sB1[t] = __ldg(B1 + t);
    for (int i = t; i < WND; i += TCB) sB2[i] = __ldg(B2 + i);
    // W2 [32][640] -> k-pair-packed bf16 hi/lo: pB[n][p] = (W2[2p][n], W2[2p+1][n])
    for (int idx = t; idx < WND * 16; idx += TCB) {
        int n = idx >> 4, p = idx & 15;
        float w0 = __ldg(W2 + (2 * p) * WND + n);
        float w1 = __ldg(W2 + (2 * p + 1) * WND + n);
        __nv_bfloat16 h0 = __float2bfloat16(w0), h1 = __float2bfloat16(w1);
        float l0 = w0 - __bfloat162float(h0), l1 = w1 - __bfloat162float(h1);
        pBH[n * 20 + p] = (unsigned)__bfloat16_as_ushort(h0) | ((unsigned)__bfloat16_as_ushort(h1) << 16);
        pBL[n * 20 + p] = pkbf(l0, l1);
    }
    __syncthreads();

    // ldmatrix per-lane address components
    const unsigned aHu = s2u(pAH), aLu = s2u(pAL);
    const unsigned bHu = s2u(pBH), bLu = s2u(pBL);
    const int arow = lane & 15, ahw = lane >> 4;    // A: row sel + k-half word
    const int brow = lane & 7,  bhw = lane >> 3;    // B: row sel + k-quarter word
    const unsigned aoff = (unsigned)(arow * 80 + ahw * 16);   // bytes within pA
    const unsigned boff = (unsigned)(brow * 80 + bhw * 16);   // bytes within pB

    const int n_chunks = (n_edges + EC - 1) / EC;
    for (int c = blockIdx.x; c < n_chunks; c += gridDim.x) {
        const int c0 = c * EC;
        // stage ef
        {
            const int lim = n_edges * HED;
            for (int l = t; l < EC * HED; l += TCB) {
                int g = c0 * HED + l;
                stage[(l >> 5) * 69 + (l & 31)] = (g < lim) ? __ldg(ef + g) : 0.f;
            }
        }
        __syncthreads();

        // MLP1: thread computes h[hf*16 .. hf*16+16) for edge er
        {
            float hreg[16];
            const float* myef = stage + er * 69;
            const float* b1h = sB1 + hf * 16;
#pragma unroll
            for (int j = 0; j < 16; j++) hreg[j] = b1h[j];
#pragma unroll 4
            for (int i = 0; i < 32; i++) {
                float x = myef[i];
#pragma unroll
                for (int j4 = 0; j4 < 4; j4++) {
                    float4 r = *reinterpret_cast<const float4*>(sW1 + i * 32 + hf * 16 + 4 * j4);
                    hreg[4 * j4 + 0] = fmaf(x, r.x, hreg[4 * j4 + 0]);
                    hreg[4 * j4 + 1] = fmaf(x, r.y, hreg[4 * j4 + 1]);
                    hreg[4 * j4 + 2] = fmaf(x, r.z, hreg[4 * j4 + 2]);
                    hreg[4 * j4 + 3] = fmaf(x, r.w, hreg[4 * j4 + 3]);
                }
            }
#pragma unroll
            for (int j = 0; j < 16; j++) hreg[j] = fmaxf(hreg[j], 0.f);
            // pA pairs p = hf*8 + [0..8)
#pragma unroll
            for (int p = 0; p < 8; p++) {
                float x = hreg[2 * p], y = hreg[2 * p + 1];
                __nv_bfloat16 hx = __float2bfloat16(x), hy = __float2bfloat16(y);
                pAH[er * 20 + hf * 8 + p] =
                    (unsigned)__bfloat16_as_ushort(hx) | ((unsigned)__bfloat16_as_ushort(hy) << 16);
                pAL[er * 20 + hf * 8 + p] = pkbf(x - __bfloat162float(hx), y - __bfloat162float(hy));
            }
        }
        __syncthreads();   // all ef reads done; pA complete

        // phase C: half 0 writes atom features, scalar coefs, sh into stage row er
        const int e = c0 + er;
        const bool valid = e < n_edges;
        int src = 0;
        if (hf == 0) {
            float shs = 0.f, s0 = 0.f, s1 = 0.f, s2 = 0.f;
            float* stw = stage + er * 69;
            if (valid) {
                int dst = __ldg(ei + e);
                src = __ldg(ei + n_edges + e);
                float4 s4 = __ldg(reinterpret_cast<const float4*>(sh) + e);
                shs = s4.x; s0 = s4.y; s1 = s4.z; s2 = s4.w;
                const float4* ar = reinterpret_cast<const float4*>(atom + dst * DD);
#pragma unroll
                for (int i = 0; i < 10; i++) {
                    float4 v = __ldg(ar + i);
                    stw[4 * i] = v.x; stw[4 * i + 1] = v.y;
                    stw[4 * i + 2] = v.z; stw[4 * i + 3] = v.w;
                }
            } else {
#pragma unroll
                for (int i = 0; i < 40; i++) stw[i] = 0.f;
            }
            stw[64] = shs; stw[65] = s0; stw[66] = s1; stw[67] = s2;
#pragma unroll
            for (int i = 0; i < 16; i++) stw[40 + i] = stw[i] * shs;
#pragma unroll
            for (int i = 0; i < 8; i++) {
                const float* xv = stw + 16 + 3 * i;
                stw[56 + i] = kC110 * (xv[0] * s0 + xv[1] * s1 + xv[2] * s2);
            }
        }
        __syncthreads();

        const float* st = stage + er * 69;
        float os[16], ov[24];
#pragma unroll
        for (int o = 0; o < 16; o++) os[o] = 0.f;
#pragma unroll
        for (int o = 0; o < 24; o++) ov[o] = 0.f;

        for (int tile = 0; tile < 5; tile++) {
            // ---- mma: warp w covers cols [w*16, w*16+16) of the 128-col supertile
            unsigned bh[2][4], bl[2][4];
#pragma unroll
            for (int nn = 0; nn < 2; nn++) {
                unsigned nbase = (unsigned)((tile * 128 + w * 16 + nn * 8) * 80);
                ldm4(bh[nn][0], bh[nn][1], bh[nn][2], bh[nn][3], bHu + nbase + boff);
                ldm4(bl[nn][0], bl[nn][1], bl[nn][2], bl[nn][3], bLu + nbase + boff);
            }
            for (int mt = 0; mt < 8; mt++) {
                const int r0 = mt * 16 + (lane >> 2);
                unsigned mbase = (unsigned)(mt * 16 * 80);
                unsigned ah0, ah1, ah2, ah3, ah4, ah5, ah6, ah7;
                unsigned al0, al1, al2, al3, al4, al5, al6, al7;
                ldm4(ah0, ah1, ah2, ah3, aHu + mbase + aoff);
                ldm4(ah4, ah5, ah6, ah7, aHu + mbase + aoff + 32);
                ldm4(al0, al1, al2, al3, aLu + mbase + aoff);
                ldm4(al4, al5, al6, al7, aLu + mbase + aoff + 32);
#pragma unroll
                for (int nn = 0; nn < 2; nn++) {
                    float a0 = 0.f, a1 = 0.f, a2 = 0.f, a3 = 0.f;   // chain A
                    float b0 = 0.f, b1 = 0.f, b2 = 0.f, b3 = 0.f;   // chain B
                    mma16816(a0, a1, a2, a3, ah0, ah1, ah2, ah3, bh[nn][0], bh[nn][1]);
                    mma16816(a0, a1, a2, a3, ah4, ah5, ah6, ah7, bh[nn][2], bh[nn][3]);
                    mma16816(a0, a1, a2, a3, ah0, ah1, ah2, ah3, bl[nn][0], bl[nn][1]);
                    mma16816(b0, b1, b2, b3, ah4, ah5, ah6, ah7, bl[nn][2], bl[nn][3]);
                    mma16816(b0, b1, b2, b3, al0, al1, al2, al3, bh[nn][0], bh[nn][1]);
                    mma16816(b0, b1, b2, b3, al4, al5, al6, al7, bh[nn][2], bh[nn][3]);
                    int col = w * 16 + nn * 8 + (lane & 3) * 2;
                    float* r0p = Dsm + r0 * 129 + col;
                    float* r1p = Dsm + (r0 + 8) * 129 + col;
                    r0p[0] = a0 + b0; r0p[1] = a1 + b1;
                    r1p[0] = a2 + b2; r1p[1] = a3 + b3;
                }
            }
            __syncthreads();

            // ---- epilogue: thread (er, hf) consumes half the columns of row er
            const float* myD = Dsm + er * 129;
            if (tile < 3) {
                for (int ib = hf * 4; ib < hf * 4 + 4; ib++) {
                    float aa = st[40 + tile * 8 + ib];
#pragma unroll
                    for (int o = 0; o < 16; o++) {
                        int n = tile * 128 + ib * 16 + o;
                        os[o] = fmaf(myD[ib * 16 + o] + sB2[n], aa, os[o]);
                    }
                }
            } else {
                float shs = st[64], s0 = st[65], s1 = st[66], s2 = st[67];
                for (int ii = hf * 8; ii < hf * 8 + 8; ii++) {
                    int i3 = (tile - 3) * 16 + ii;
                    float m0, m1, m2;
                    if (i3 < 16) {
                        float x = st[i3];
                        m0 = x * s0; m1 = x * s1; m2 = x * s2;
                    } else if (i3 < 24) {
                        const float* xv = st + 16 + 3 * (i3 - 16);
                        m0 = xv[0] * shs; m1 = xv[1] * shs; m2 = xv[2] * shs;
                    } else {
                        const float* xv = st + 16 + 3 * (i3 - 24);
                        m0 = kC111 * (xv[1] * s2 - xv[2] * s1);
                        m1 = kC111 * (xv[2] * s0 - xv[0] * s2);
                        m2 = kC111 * (xv[0] * s1 - xv[1] * s0);
                    }
#pragma unroll
                    for (int oo = 0; oo < 8; oo++) {
                        int n = 384 + i3 * 8 + oo;
                        float wv = myD[ii * 8 + oo] + sB2[n];
                        ov[3 * oo + 0] = fmaf(wv, m0, ov[3 * oo + 0]);
                        ov[3 * oo + 1] = fmaf(wv, m1, ov[3 * oo + 1]);
                        ov[3 * oo + 2] = fmaf(wv, m2, ov[3 * oo + 2]);
                    }
                }
            }
            __syncthreads();
        }

        // merge halves: half 1 writes partials to Dsm, half 0 adds and emits
        if (hf == 1) {
            float* mrow = Dsm + er * 129;
#pragma unroll
            for (int o = 0; o < 16; o++) mrow[o] = os[o];
#pragma unroll
            for (int cc = 0; cc < 24; cc++) mrow[16 + cc] = ov[cc];
        }
        __syncthreads();
        if (hf == 0 && valid) {
            const float* mrow = Dsm + er * 129;
#pragma unroll
            for (int o = 0; o < 16; o++) os[o] += mrow[o];
#pragma unroll
            for (int cc = 0; cc < 24; cc++) ov[cc] += mrow[16 + cc];

            if (IS_K) {
                const float* q = d_qnode + src * DD;
                float attn = 0.f;
#pragma unroll
                for (int o = 0; o < 16; o++) attn = fmaf(os[o], __ldg(q + o), attn);
#pragma unroll
                for (int cc = 0; cc < 24; cc++) attn = fmaf(ov[cc], __ldg(q + 16 + cc), attn);
                d_attn[e] = attn;
                atomicMax(&d_nmax[src], encf(attn));
            } else {
#pragma unroll
                for (int o = 0; o < 16; o++) d_vedge[o * n_edges + e] = os[o];
#pragma unroll
                for (int cc = 0; cc < 24; cc++) d_vedge[(16 + cc) * n_edges + e] = ov[cc];
            }
        }
        __syncthreads();
    }
}

__global__ void k_soft(const int* __restrict__ ei, int n_edges) {
    int e = blockIdx.x * blockDim.x + threadIdx.x;
    if (e >= n_edges) return;
    int src = __ldg(ei + n_edges + e);
    float m = decf(d_nmax[src]);
    float a = expf(d_attn[e] - m);
    atomicAdd(&d_denom[src], a);
    float* u = d_upd + src * DD;
#pragma unroll
    for (int c = 0; c < DD; c++)
        atomicAdd(u + c, a * d_vedge[c * n_edges + e]);
}

__global__ void k_stats(const float* __restrict__ atom, int n_nodes) {
    __shared__ float red[40];
    int t = threadIdx.x;
    if (t < 40) red[t] = 0.f;
    __syncthreads();
    int n = blockIdx.x * blockDim.x + t;
    float y[40];
    if (n < n_nodes) {
        float den = d_denom[n];
        float inv = den > 0.f ? 1.f / den : 0.f;
#pragma unroll
        for (int c = 0; c < 40; c++) {
            y[c] = atom[n * DD + c] + d_upd[n * DD + c] * inv;
            d_ybuf[n * DD + c] = y[c];
        }
    } else {
#pragma unroll
        for (int c = 0; c < 40; c++) y[c] = 0.f;
    }
    const unsigned full = 0xffffffffu;
#pragma unroll
    for (int c = 0; c < 16; c++) {
        float v = y[c], v2 = v * v;
#pragma unroll
        for (int o = 16; o > 0; o >>= 1) {
            v  += __shfl_down_sync(full, v, o);
            v2 += __shfl_down_sync(full, v2, o);
        }
        if ((t & 31) == 0) { atomicAdd(&red[c], v); atomicAdd(&red[16 + c], v2); }
    }
#pragma unroll
    for (int i = 0; i < 8; i++) {
        float v = y[16 + 3 * i] * y[16 + 3 * i] + y[17 + 3 * i] * y[17 + 3 * i]
                + y[18 + 3 * i] * y[18 + 3 * i];
#pragma unroll
        for (int o = 16; o > 0; o >>= 1) v += __shfl_down_sync(full, v, o);
        if ((t & 31) == 0) atomicAdd(&red[32 + i], v);
    }
    __syncthreads();
    if (t < 40) atomicAdd(&d_gstats[t], red[t]);
}

__global__ void k_bn(const float* __restrict__ ws, const float* __restrict__ bs,
                     const float* __restrict__ wv, int n_nodes) {
    int t = threadIdx.x;
    float N = (float)n_nodes;
    if (t < 16) {
        float mu  = d_gstats[t] / N;
        float var = d_gstats[16 + t] / N - mu * mu;
        float A = __ldg(ws + t) / sqrtf(var + EPSV);
        d_bnp[t] = A;
        d_bnp[16 + t] = __ldg(bs + t) - mu * A;
    } else if (t < 24) {
        int i = t - 16;
        float norm = d_gstats[32 + i] / (3.f * N);
        d_bnp[32 + i] = __ldg(wv + i) / sqrtf(norm + EPSV);
    }
}

__global__ void k_out(float* __restrict__ out, int n_nodes) {
    int idx = blockIdx.x * blockDim.x + threadIdx.x;
    if (idx >= n_nodes * DD) return;
    int c = idx % DD;
    float y = d_ybuf[idx];
    out[idx] = (c < 16) ? (y * d_bnp[c] + d_bnp[16 + c])
                        : (y * d_bnp[32 + (c - 16) / 3]);
}

__global__ void k_copy(const float* __restrict__ src, float* __restrict__ dst, int n4) {
    int i = blockIdx.x * blockDim.x + threadIdx.x;
    if (i < n4)
        reinterpret_cast<float4*>(dst)[i] = __ldg(reinterpret_cast<const float4*>(src) + i);
}

extern "C" void kernel_launch(void* const* d_in, const int* in_sizes, int n_in,
                              void* d_out, int out_size) {
    const float* atom = (const float*)d_in[0];
    const float* ef   = (const float*)d_in[1];
    const float* sh   = (const float*)d_in[2];
    const float* Wqs  = (const float*)d_in[3];
    const float* Wqv  = (const float*)d_in[4];
    const float* kw1  = (const float*)d_in[5];
    const float* kb1  = (const float*)d_in[6];
    const float* kw2  = (const float*)d_in[7];
    const float* kb2  = (const float*)d_in[8];
    const float* vw1  = (const float*)d_in[9];
    const float* vb1  = (const float*)d_in[10];
    const float* vw2  = (const float*)d_in[11];
    const float* vb2  = (const float*)d_in[12];
    const float* bnws = (const float*)d_in[13];
    const float* bnbs = (const float*)d_in[14];
    const float* bnwv = (const float*)d_in[15];
    const int*   ei   = (const int*)d_in[16];

    int n_nodes = in_sizes[0] / DD;
    int n_edges = in_sizes[1] / HED;
    float* out = (float*)d_out;

    cudaFuncSetAttribute(k_edge_mma<true>,  cudaFuncAttributeMaxDynamicSharedMemorySize, SM_TC);
    cudaFuncSetAttribute(k_edge_mma<false>, cudaFuncAttributeMaxDynamicSharedMemorySize, SM_TC);

    k_init<<<(n_nodes * DD + 255) / 256, 256>>>(n_nodes);
    k_qnode<<<(n_nodes + 255) / 256, 256>>>(atom, Wqs, Wqv, n_nodes);

    k_edge_mma<true><<<148, TCB, SM_TC>>>(atom, ef, sh, ei, kw1, kb1, kw2, kb2, n_edges);
    k_edge_mma<false><<<148, TCB, SM_TC>>>(atom, ef, sh, ei, vw1, vb1, vw2, vb2, n_edges);

    k_soft<<<(n_edges + 255) / 256, 256>>>(ei, n_edges);
    k_stats<<<(n_nodes + 255) / 256, 256>>>(atom, n_nodes);
    k_bn<<<1, 64>>>(bnws, bnbs, bnwv, n_nodes);
    k_out<<<(n_nodes * DD + 255) / 256, 256>>>(out, n_nodes);

    int n4 = (n_edges * HED) / 4;
    k_copy<<<(n4 + 255) / 256, 256>>>(ef, out + n_nodes * DD, n4);
}

// round 14
// speedup vs baseline: 1.5665x; 1.0254x over previous
#include <cuda_runtime.h>
#include <cuda_bf16.h>

#define NSD 16
#define NVD 8
#define HED 32
#define DD  40
#define WND 640
#define MAXN 10000
#define MAXE 160000
#define EPSV 1e-5f
#define EC   128
#define TCB  512

// smem float offsets
#define OFF_W1  0
#define OFF_B1  1024
#define OFF_B2  1056
#define OFF_STG 1696            // stage: 128 rows x 65 (atom 0..39, coef 40..63)
#define OFF_PAH 10016           // A pairs hi: 128 x 20 u32
#define OFF_PAL 12576
#define OFF_PBH 15136           // B pairs hi: 640 x 20 u32
#define OFF_PBL 27936
#define OFF_DSM 40736           // D tile: 128 x 132 f32 (also merge buffer)
#define SM_FLT  57632
#define SM_TC   (SM_FLT * 4)
#define DST     132

__device__ __constant__ float kC110 = 0.57735026918962576f;
__device__ __constant__ float kC111 = 0.70710678118654752f;

__device__ float    d_qnode[MAXN * DD];
__device__ float    d_attn [MAXE];
__device__ float    d_vedge[MAXE * DD];
__device__ unsigned d_nmax [MAXN];
__device__ float    d_denom[MAXN];
__device__ float    d_upd  [MAXN * DD];
__device__ float    d_ybuf [MAXN * DD];
__device__ float    d_gstats[48];
__device__ float    d_bnp  [48];

__device__ __forceinline__ unsigned encf(float f) {
    unsigned u = __float_as_uint(f);
    return (u & 0x80000000u) ? ~u : (u | 0x80000000u);
}
__device__ __forceinline__ float decf(unsigned u) {
    return (u & 0x80000000u) ? __uint_as_float(u ^ 0x80000000u) : __uint_as_float(~u);
}
__device__ __forceinline__ unsigned s2u(const void* p) {
    unsigned a;
    asm("{ .reg .u64 t; cvta.to.shared.u64 t, %1; cvt.u32.u64 %0, t; }" : "=r"(a) : "l"(p));
    return a;
}

__device__ __forceinline__ void mma16816(float& d0, float& d1, float& d2, float& d3,
                                         unsigned a0, unsigned a1, unsigned a2, unsigned a3,
                                         unsigned b0, unsigned b1) {
    asm volatile(
        "mma.sync.aligned.m16n8k16.row.col.f32.bf16.bf16.f32 "
        "{%0,%1,%2,%3}, {%4,%5,%6,%7}, {%8,%9}, {%0,%1,%2,%3};"
        : "+f"(d0), "+f"(d1), "+f"(d2), "+f"(d3)
        : "r"(a0), "r"(a1), "r"(a2), "r"(a3), "r"(b0), "r"(b1));
}
__device__ __forceinline__ void ldm4(unsigned& r0, unsigned& r1, unsigned& r2, unsigned& r3,
                                     unsigned addr) {
    asm volatile("ldmatrix.sync.aligned.m8n8.x4.shared.b16 {%0,%1,%2,%3}, [%4];"
                 : "=r"(r0), "=r"(r1), "=r"(r2), "=r"(r3) : "r"(addr));
}
__device__ __forceinline__ unsigned pkbf(float x, float y) {
    __nv_bfloat16 bx = __float2bfloat16(x), by = __float2bfloat16(y);
    return (unsigned)__bfloat16_as_ushort(bx) | ((unsigned)__bfloat16_as_ushort(by) << 16);
}

__global__ void k_init(int n_nodes) {
    int i = blockIdx.x * blockDim.x + threadIdx.x;
    if (i < n_nodes * DD) d_upd[i] = 0.f;
    if (i < n_nodes) { d_denom[i] = 0.f; d_nmax[i] = 0u; }
    if (i < 48) d_gstats[i] = 0.f;
}

__global__ void k_qnode(const float* __restrict__ atom, const float* __restrict__ Wqs,
                        const float* __restrict__ Wqv, int n_nodes) {
    int n = blockIdx.x * blockDim.x + threadIdx.x;
    if (n >= n_nodes) return;
    const float* a = atom + n * DD;
    float qs[16], qv[24];
#pragma unroll
    for (int o = 0; o < 16; o++) qs[o] = 0.f;
#pragma unroll
    for (int c = 0; c < 24; c++) qv[c] = 0.f;
    for (int i = 0; i < 16; i++) {
        float x = __ldg(a + i);
#pragma unroll
        for (int o = 0; o < 16; o++) qs[o] = fmaf(x, __ldg(Wqs + i * 16 + o), qs[o]);
    }
    for (int i = 0; i < 8; i++) {
        float x0 = __ldg(a + 16 + 3 * i), x1 = __ldg(a + 17 + 3 * i), x2 = __ldg(a + 18 + 3 * i);
#pragma unroll
        for (int o = 0; o < 8; o++) {
            float w = __ldg(Wqv + i * 8 + o);
            qv[3 * o + 0] = fmaf(w, x0, qv[3 * o + 0]);
            qv[3 * o + 1] = fmaf(w, x1, qv[3 * o + 1]);
            qv[3 * o + 2] = fmaf(w, x2, qv[3 * o + 2]);
        }
    }
    float* q = d_qnode + n * DD;
#pragma unroll
    for (int o = 0; o < 16; o++) q[o] = qs[o];
#pragma unroll
    for (int c = 0; c < 24; c++) q[16 + c] = qv[c];
}

template <bool IS_K>
__global__ void __launch_bounds__(TCB, 1) k_edge_mma(
    const float* __restrict__ atom, const float* __restrict__ ef,
    const float* __restrict__ sh, const int* __restrict__ ei,
    const float* __restrict__ W1, const float* __restrict__ B1,
    const float* __restrict__ W2, const float* __restrict__ B2,
    int n_edges)
{
    extern __shared__ float sm[];
    float* sW1 = sm + OFF_W1;
    float* sB1 = sm + OFF_B1;
    float* sB2 = sm + OFF_B2;
    float* stage = sm + OFF_STG;
    unsigned* pAH = (unsigned*)(sm + OFF_PAH);
    unsigned* pAL = (unsigned*)(sm + OFF_PAL);
    unsigned* pBH = (unsigned*)(sm + OFF_PBH);
    unsigned* pBL = (unsigned*)(sm + OFF_PBL);
    float* Dsm = sm + OFF_DSM;

    const int t = threadIdx.x;
    const int w = t >> 5, lane = t & 31;
    const int er = t & 127;     // edge row (MLP / epilogue)
    const int qf = t >> 7;      // quarter index (0..3)

    for (int i = t; i < 1024; i += TCB) sW1[i] = __ldg(W1 + i);
    if (t < 32) sB1[t] = __ldg(B1 + t);
    for (int i = t; i < WND; i += TCB) sB2[i] = __ldg(B2 + i);
    // W2 [32][640] -> k-pair-packed bf16 hi/lo: pB[n][p] = (W2[2p][n], W2[2p+1][n])
    for (int idx = t; idx < WND * 16; idx += TCB) {
        int n = idx >> 4, p = idx & 15;
        float w0 = __ldg(W2 + (2 * p) * WND + n);
        float w1 = __ldg(W2 + (2 * p + 1) * WND + n);
        __nv_bfloat16 h0 = __float2bfloat16(w0), h1 = __float2bfloat16(w1);
        float l0 = w0 - __bfloat162float(h0), l1 = w1 - __bfloat162float(h1);
        pBH[n * 20 + p] = (unsigned)__bfloat16_as_ushort(h0) | ((unsigned)__bfloat16_as_ushort(h1) << 16);
        pBL[n * 20 + p] = pkbf(l0, l1);
    }
    __syncthreads();

    // ldmatrix per-lane address components
    const unsigned aHu = s2u(pAH), aLu = s2u(pAL);
    const unsigned bHu = s2u(pBH), bLu = s2u(pBL);
    const int arow = lane & 15, ahw = lane >> 4;
    const int brow = lane & 7,  bhw = lane >> 3;
    const unsigned aoff = (unsigned)(arow * 80 + ahw * 16);
    const unsigned boff = (unsigned)(brow * 80 + bhw * 16);

    const int n_chunks = (n_edges + EC - 1) / EC;
    for (int c = blockIdx.x; c < n_chunks; c += gridDim.x) {
        const int c0 = c * EC;
        // stage ef
        {
            const int lim = n_edges * HED;
            for (int l = t; l < EC * HED; l += TCB) {
                int g = c0 * HED + l;
                stage[(l >> 5) * 65 + (l & 31)] = (g < lim) ? __ldg(ef + g) : 0.f;
            }
        }
        __syncthreads();

        // MLP1: thread computes h[qf*8 .. qf*8+8) for edge er
        {
            float hreg[8];
            const float* myef = stage + er * 65;
            const float* b1h = sB1 + qf * 8;
#pragma unroll
            for (int j = 0; j < 8; j++) hreg[j] = b1h[j];
#pragma unroll 4
            for (int i = 0; i < 32; i++) {
                float x = myef[i];
#pragma unroll
                for (int j2 = 0; j2 < 2; j2++) {
                    float4 r = *reinterpret_cast<const float4*>(sW1 + i * 32 + qf * 8 + 4 * j2);
                    hreg[4 * j2 + 0] = fmaf(x, r.x, hreg[4 * j2 + 0]);
                    hreg[4 * j2 + 1] = fmaf(x, r.y, hreg[4 * j2 + 1]);
                    hreg[4 * j2 + 2] = fmaf(x, r.z, hreg[4 * j2 + 2]);
                    hreg[4 * j2 + 3] = fmaf(x, r.w, hreg[4 * j2 + 3]);
                }
            }
#pragma unroll
            for (int j = 0; j < 8; j++) hreg[j] = fmaxf(hreg[j], 0.f);
#pragma unroll
            for (int p = 0; p < 4; p++) {
                float x = hreg[2 * p], y = hreg[2 * p + 1];
                __nv_bfloat16 hx = __float2bfloat16(x), hy = __float2bfloat16(y);
                pAH[er * 20 + qf * 4 + p] =
                    (unsigned)__bfloat16_as_ushort(hx) | ((unsigned)__bfloat16_as_ushort(hy) << 16);
                pAL[er * 20 + qf * 4 + p] = pkbf(x - __bfloat162float(hx), y - __bfloat162float(hy));
            }
        }
        __syncthreads();   // all ef reads done; pA complete

        // phase C: quarter 0 writes atom features + scalar coefs into stage row er
        const int e = c0 + er;
        const bool valid = e < n_edges;
        const int ecl = valid ? e : (n_edges - 1);
        int src = 0;
        if (qf == 0) {
            float shs = 0.f, s0 = 0.f, s1 = 0.f, s2 = 0.f;
            float* stw = stage + er * 65;
            if (valid) {
                int dst = __ldg(ei + e);
                src = __ldg(ei + n_edges + e);
                float4 s4 = __ldg(reinterpret_cast<const float4*>(sh) + e);
                shs = s4.x; s0 = s4.y; s1 = s4.z; s2 = s4.w;
                const float4* ar = reinterpret_cast<const float4*>(atom + dst * DD);
#pragma unroll
                for (int i = 0; i < 10; i++) {
                    float4 v = __ldg(ar + i);
                    stw[4 * i] = v.x; stw[4 * i + 1] = v.y;
                    stw[4 * i + 2] = v.z; stw[4 * i + 3] = v.w;
                }
            } else {
#pragma unroll
                for (int i = 0; i < 40; i++) stw[i] = 0.f;
            }
#pragma unroll
            for (int i = 0; i < 16; i++) stw[40 + i] = stw[i] * shs;
#pragma unroll
            for (int i = 0; i < 8; i++) {
                const float* xv = stw + 16 + 3 * i;
                stw[56 + i] = kC110 * (xv[0] * s0 + xv[1] * s1 + xv[2] * s2);
            }
        }
        // every thread fetches sh for its row (L1-cached, clamped)
        float4 shv = __ldg(reinterpret_cast<const float4*>(sh) + ecl);
        if (!valid) { shv.x = 0.f; shv.y = 0.f; shv.z = 0.f; shv.w = 0.f; }
        __syncthreads();

        const float* st = stage + er * 65;
        float os[16], ov[24];
#pragma unroll
        for (int o = 0; o < 16; o++) os[o] = 0.f;
#pragma unroll
        for (int o = 0; o < 24; o++) ov[o] = 0.f;

        for (int tile = 0; tile < 5; tile++) {
            // ---- mma: warp w covers cols [w*8, w*8+8) of the 128-col supertile
            unsigned bh[4], bl[4];
            {
                unsigned nbase = (unsigned)((tile * 128 + w * 8) * 80);
                ldm4(bh[0], bh[1], bh[2], bh[3], bHu + nbase + boff);
                ldm4(bl[0], bl[1], bl[2], bl[3], bLu + nbase + boff);
            }
            for (int mt = 0; mt < 8; mt++) {
                const int r0 = mt * 16 + (lane >> 2);
                unsigned mbase = (unsigned)(mt * 16 * 80);
                unsigned ah0, ah1, ah2, ah3, ah4, ah5, ah6, ah7;
                unsigned al0, al1, al2, al3, al4, al5, al6, al7;
                ldm4(ah0, ah1, ah2, ah3, aHu + mbase + aoff);
                ldm4(ah4, ah5, ah6, ah7, aHu + mbase + aoff + 32);
                ldm4(al0, al1, al2, al3, aLu + mbase + aoff);
                ldm4(al4, al5, al6, al7, aLu + mbase + aoff + 32);
                float a0 = 0.f, a1 = 0.f, a2 = 0.f, a3 = 0.f;
                float b0 = 0.f, b1 = 0.f, b2 = 0.f, b3 = 0.f;
                mma16816(a0, a1, a2, a3, ah0, ah1, ah2, ah3, bh[0], bh[1]);
                mma16816(a0, a1, a2, a3, ah4, ah5, ah6, ah7, bh[2], bh[3]);
                mma16816(a0, a1, a2, a3, ah0, ah1, ah2, ah3, bl[0], bl[1]);
                mma16816(b0, b1, b2, b3, ah4, ah5, ah6, ah7, bl[2], bl[3]);
                mma16816(b0, b1, b2, b3, al0, al1, al2, al3, bh[0], bh[1]);
                mma16816(b0, b1, b2, b3, al4, al5, al6, al7, bh[2], bh[3]);
                int col = w * 8 + (lane & 3) * 2;
                float* r0p = Dsm + r0 * DST + col;
                float* r1p = Dsm + (r0 + 8) * DST + col;
                r0p[0] = a0 + b0; r0p[1] = a1 + b1;
                r1p[0] = a2 + b2; r1p[1] = a3 + b3;
            }
            __syncthreads();

            // ---- epilogue: thread (er, qf) consumes a quarter of row er's columns
            const float* myD = Dsm + er * DST;
            if (tile < 3) {
#pragma unroll
                for (int q2 = 0; q2 < 2; q2++) {
                    int ib = qf * 2 + q2;
                    float aa = st[40 + tile * 8 + ib];
#pragma unroll
                    for (int o4 = 0; o4 < 4; o4++) {
                        float4 d4 = *reinterpret_cast<const float4*>(myD + ib * 16 + 4 * o4);
                        float4 b4 = *reinterpret_cast<const float4*>(sB2 + tile * 128 + ib * 16 + 4 * o4);
                        os[4 * o4 + 0] = fmaf(d4.x + b4.x, aa, os[4 * o4 + 0]);
                        os[4 * o4 + 1] = fmaf(d4.y + b4.y, aa, os[4 * o4 + 1]);
                        os[4 * o4 + 2] = fmaf(d4.z + b4.z, aa, os[4 * o4 + 2]);
                        os[4 * o4 + 3] = fmaf(d4.w + b4.w, aa, os[4 * o4 + 3]);
                    }
                }
            } else {
                float shs = shv.x, s0 = shv.y, s1 = shv.z, s2 = shv.w;
#pragma unroll
                for (int q4 = 0; q4 < 4; q4++) {
                    int ii = qf * 4 + q4;
                    int i3 = (tile - 3) * 16 + ii;
                    float m0, m1, m2;
                    if (i3 < 16) {
                        float x = st[i3];
                        m0 = x * s0; m1 = x * s1; m2 = x * s2;
                    } else if (i3 < 24) {
                        const float* xv = st + 16 + 3 * (i3 - 16);
                        m0 = xv[0] * shs; m1 = xv[1] * shs; m2 = xv[2] * shs;
                    } else {
                        const float* xv = st + 16 + 3 * (i3 - 24);
                        m0 = kC111 * (xv[1] * s2 - xv[2] * s1);
                        m1 = kC111 * (xv[2] * s0 - xv[0] * s2);
                        m2 = kC111 * (xv[0] * s1 - xv[1] * s0);
                    }
                    float4 d4a = *reinterpret_cast<const float4*>(myD + ii * 8);
                    float4 d4b = *reinterpret_cast<const float4*>(myD + ii * 8 + 4);
                    float dv[8] = {d4a.x, d4a.y, d4a.z, d4a.w, d4b.x, d4b.y, d4b.z, d4b.w};
#pragma unroll
                    for (int oo = 0; oo < 8; oo++) {
                        int n = 384 + i3 * 8 + oo;
                        float wv = dv[oo] + sB2[n];
                        ov[3 * oo + 0] = fmaf(wv, m0, ov[3 * oo + 0]);
                        ov[3 * oo + 1] = fmaf(wv, m1, ov[3 * oo + 1]);
                        ov[3 * oo + 2] = fmaf(wv, m2, ov[3 * oo + 2]);
                    }
                }
            }
            __syncthreads();
        }

        // merge quarters: qf 1..3 write partials, qf 0 adds and emits
        if (qf != 0) {
            float* mrow = Dsm + er * DST + (qf - 1) * 44;
#pragma unroll
            for (int o = 0; o < 16; o++) mrow[o] = os[o];
#pragma unroll
            for (int cc = 0; cc < 24; cc++) mrow[16 + cc] = ov[cc];
        }
        __syncthreads();
        if (qf == 0 && valid) {
            const float* mrow = Dsm + er * DST;
#pragma unroll
            for (int o = 0; o < 16; o++) os[o] += mrow[o] + mrow[44 + o] + mrow[88 + o];
#pragma unroll
            for (int cc = 0; cc < 24; cc++) ov[cc] += mrow[16 + cc] + mrow[60 + cc] + mrow[104 + cc];

            if (IS_K) {
                const float* q = d_qnode + src * DD;
                float attn = 0.f;
#pragma unroll
                for (int o = 0; o < 16; o++) attn = fmaf(os[o], __ldg(q + o), attn);
#pragma unroll
                for (int cc = 0; cc < 24; cc++) attn = fmaf(ov[cc], __ldg(q + 16 + cc), attn);
                d_attn[e] = attn;
                atomicMax(&d_nmax[src], encf(attn));
            } else {
#pragma unroll
                for (int o = 0; o < 16; o++) d_vedge[o * n_edges + e] = os[o];
#pragma unroll
                for (int cc = 0; cc < 24; cc++) d_vedge[(16 + cc) * n_edges + e] = ov[cc];
            }
        }
        __syncthreads();
    }
}

__global__ void k_soft(const int* __restrict__ ei, int n_edges) {
    int e = blockIdx.x * blockDim.x + threadIdx.x;
    if (e >= n_edges) return;
    int src = __ldg(ei + n_edges + e);
    float m = decf(d_nmax[src]);
    float a = expf(d_attn[e] - m);
    atomicAdd(&d_denom[src], a);
    float* u = d_upd + src * DD;
#pragma unroll
    for (int c = 0; c < DD; c++)
        atomicAdd(u + c, a * d_vedge[c * n_edges + e]);
}

__global__ void k_stats(const float* __restrict__ atom, int n_nodes) {
    __shared__ float red[40];
    int t = threadIdx.x;
    if (t < 40) red[t] = 0.f;
    __syncthreads();
    int n = blockIdx.x * blockDim.x + t;
    float y[40];
    if (n < n_nodes) {
        float den = d_denom[n];
        float inv = den > 0.f ? 1.f / den : 0.f;
#pragma unroll
        for (int c = 0; c < 40; c++) {
            y[c] = atom[n * DD + c] + d_upd[n * DD + c] * inv;
            d_ybuf[n * DD + c] = y[c];
        }
    } else {
#pragma unroll
        for (int c = 0; c < 40; c++) y[c] = 0.f;
    }
    const unsigned full = 0xffffffffu;
#pragma unroll
    for (int c = 0; c < 16; c++) {
        float v = y[c], v2 = v * v;
#pragma unroll
        for (int o = 16; o > 0; o >>= 1) {
            v  += __shfl_down_sync(full, v, o);
            v2 += __shfl_down_sync(full, v2, o);
        }
        if ((t & 31) == 0) { atomicAdd(&red[c], v); atomicAdd(&red[16 + c], v2); }
    }
#pragma unroll
    for (int i = 0; i < 8; i++) {
        float v = y[16 + 3 * i] * y[16 + 3 * i] + y[17 + 3 * i] * y[17 + 3 * i]
                + y[18 + 3 * i] * y[18 + 3 * i];
#pragma unroll
        for (int o = 16; o > 0; o >>= 1) v += __shfl_down_sync(full, v, o);
        if ((t & 31) == 0) atomicAdd(&red[32 + i], v);
    }
    __syncthreads();
    if (t < 40) atomicAdd(&d_gstats[t], red[t]);
}

__global__ void k_bn(const float* __restrict__ ws, const float* __restrict__ bs,
                     const float* __restrict__ wv, int n_nodes) {
    int t = threadIdx.x;
    float N = (float)n_nodes;
    if (t < 16) {
        float mu  = d_gstats[t] / N;
        float var = d_gstats[16 + t] / N - mu * mu;
        float A = __ldg(ws + t) / sqrtf(var + EPSV);
        d_bnp[t] = A;
        d_bnp[16 + t] = __ldg(bs + t) - mu * A;
    } else if (t < 24) {
        int i = t - 16;
        float norm = d_gstats[32 + i] / (3.f * N);
        d_bnp[32 + i] = __ldg(wv + i) / sqrtf(norm + EPSV);
    }
}

__global__ void k_out(float* __restrict__ out, int n_nodes) {
    int idx = blockIdx.x * blockDim.x + threadIdx.x;
    if (idx >= n_nodes * DD) return;
    int c = idx % DD;
    float y = d_ybuf[idx];
    out[idx] = (c < 16) ? (y * d_bnp[c] + d_bnp[16 + c])
                        : (y * d_bnp[32 + (c - 16) / 3]);
}

__global__ void k_copy(const float* __restrict__ src, float* __restrict__ dst, int n4) {
    int i = blockIdx.x * blockDim.x + threadIdx.x;
    if (i < n4)
        reinterpret_cast<float4*>(dst)[i] = __ldg(reinterpret_cast<const float4*>(src) + i);
}

extern "C" void kernel_launch(void* const* d_in, const int* in_sizes, int n_in,
                              void* d_out, int out_size) {
    const float* atom = (const float*)d_in[0];
    const float* ef   = (const float*)d_in[1];
    const float* sh   = (const float*)d_in[2];
    const float* Wqs  = (const float*)d_in[3];
    const float* Wqv  = (const float*)d_in[4];
    const float* kw1  = (const float*)d_in[5];
    const float* kb1  = (const float*)d_in[6];
    const float* kw2  = (const float*)d_in[7];
    const float* kb2  = (const float*)d_in[8];
    const float* vw1  = (const float*)d_in[9];
    const float* vb1  = (const float*)d_in[10];
    const float* vw2  = (const float*)d_in[11];
    const float* vb2  = (const float*)d_in[12];
    const float* bnws = (const float*)d_in[13];
    const float* bnbs = (const float*)d_in[14];
    const float* bnwv = (const float*)d_in[15];
    const int*   ei   = (const int*)d_in[16];

    int n_nodes = in_sizes[0] / DD;
    int n_edges = in_sizes[1] / HED;
    float* out = (float*)d_out;

    cudaFuncSetAttribute(k_edge_mma<true>,  cudaFuncAttributeMaxDynamicSharedMemorySize, SM_TC);
    cudaFuncSetAttribute(k_edge_mma<false>, cudaFuncAttributeMaxDynamicSharedMemorySize, SM_TC);

    k_init<<<(n_nodes * DD + 255) / 256, 256>>>(n_nodes);
    k_qnode<<<(n_nodes + 255) / 256, 256>>>(atom, Wqs, Wqv, n_nodes);

    k_edge_mma<true><<<148, TCB, SM_TC>>>(atom, ef, sh, ei, kw1, kb1, kw2, kb2, n_edges);
    k_edge_mma<false><<<148, TCB, SM_TC>>>(atom, ef, sh, ei, vw1, vb1, vw2, vb2, n_edges);

    k_soft<<<(n_edges + 255) / 256, 256>>>(ei, n_edges);
    k_stats<<<(n_nodes + 255) / 256, 256>>>(atom, n_nodes);
    k_bn<<<1, 64>>>(bnws, bnbs, bnwv, n_nodes);
    k_out<<<(n_nodes * DD + 255) / 256, 256>>>(out, n_nodes);

    int n4 = (n_edges * HED) / 4;
    k_copy<<<(n4 + 255) / 256, 256>>>(ef, out + n_nodes * DD, n4);
}

// round 15
// speedup vs baseline: 1.7416x; 1.1117x over previous
#include <cuda_runtime.h>
#include <cuda_bf16.h>

#define NSD 16
#define NVD 8
#define HED 32
#define DD  40
#define WND 640
#define MAXN 10000
#define MAXE 160000
#define EPSV 1e-5f
#define EC   128
#define TCB  512

// smem float offsets
#define OFF_W1  0
#define OFF_B1  1024
#define OFF_B2  1056
#define OFF_STG 1696            // stage: 128 rows x 65 (atom 0..39, coef 40..63)
#define OFF_PAH 10016           // A pairs hi: 128 x 20 u32
#define OFF_PAL 12576
#define OFF_PBH 15136           // B pairs hi: 640 x 20 u32
#define OFF_PBL 27936
#define OFF_DSM 40736           // D tile: 128 x 132 f32 (also merge buffer)
#define SM_FLT  57632
#define SM_TC   (SM_FLT * 4)
#define DST     132

__device__ __constant__ float kC110 = 0.57735026918962576f;
__device__ __constant__ float kC111 = 0.70710678118654752f;

__device__ float    d_qnode[MAXN * DD];
__device__ float    d_attn [MAXE];
__device__ float    d_vedge[MAXE * DD];
__device__ unsigned d_nmax [MAXN];
__device__ float    d_denom[MAXN];
__device__ float    d_upd  [MAXN * DD];
__device__ float    d_ybuf [MAXN * DD];
__device__ float    d_gstats[48];
__device__ float    d_bnp  [48];

__device__ __forceinline__ unsigned encf(float f) {
    unsigned u = __float_as_uint(f);
    return (u & 0x80000000u) ? ~u : (u | 0x80000000u);
}
__device__ __forceinline__ float decf(unsigned u) {
    return (u & 0x80000000u) ? __uint_as_float(u ^ 0x80000000u) : __uint_as_float(~u);
}
__device__ __forceinline__ unsigned s2u(const void* p) {
    unsigned a;
    asm("{ .reg .u64 t; cvta.to.shared.u64 t, %1; cvt.u32.u64 %0, t; }" : "=r"(a) : "l"(p));
    return a;
}

__device__ __forceinline__ void mma16816(float& d0, float& d1, float& d2, float& d3,
                                         unsigned a0, unsigned a1, unsigned a2, unsigned a3,
                                         unsigned b0, unsigned b1) {
    asm volatile(
        "mma.sync.aligned.m16n8k16.row.col.f32.bf16.bf16.f32 "
        "{%0,%1,%2,%3}, {%4,%5,%6,%7}, {%8,%9}, {%0,%1,%2,%3};"
        : "+f"(d0), "+f"(d1), "+f"(d2), "+f"(d3)
        : "r"(a0), "r"(a1), "r"(a2), "r"(a3), "r"(b0), "r"(b1));
}
__device__ __forceinline__ void ldm4(unsigned& r0, unsigned& r1, unsigned& r2, unsigned& r3,
                                     unsigned addr) {
    asm volatile("ldmatrix.sync.aligned.m8n8.x4.shared.b16 {%0,%1,%2,%3}, [%4];"
                 : "=r"(r0), "=r"(r1), "=r"(r2), "=r"(r3) : "r"(addr));
}
__device__ __forceinline__ unsigned pkbf(float x, float y) {
    __nv_bfloat16 bx = __float2bfloat16(x), by = __float2bfloat16(y);
    return (unsigned)__bfloat16_as_ushort(bx) | ((unsigned)__bfloat16_as_ushort(by) << 16);
}

__global__ void k_init(int n_nodes) {
    int i = blockIdx.x * blockDim.x + threadIdx.x;
    if (i < n_nodes * DD) d_upd[i] = 0.f;
    if (i < n_nodes) { d_denom[i] = 0.f; d_nmax[i] = 0u; }
    if (i < 48) d_gstats[i] = 0.f;
}

__global__ void k_qnode(const float* __restrict__ atom, const float* __restrict__ Wqs,
                        const float* __restrict__ Wqv, int n_nodes) {
    int n = blockIdx.x * blockDim.x + threadIdx.x;
    if (n >= n_nodes) return;
    const float* a = atom + n * DD;
    float qs[16], qv[24];
#pragma unroll
    for (int o = 0; o < 16; o++) qs[o] = 0.f;
#pragma unroll
    for (int c = 0; c < 24; c++) qv[c] = 0.f;
    for (int i = 0; i < 16; i++) {
        float x = __ldg(a + i);
#pragma unroll
        for (int o = 0; o < 16; o++) qs[o] = fmaf(x, __ldg(Wqs + i * 16 + o), qs[o]);
    }
    for (int i = 0; i < 8; i++) {
        float x0 = __ldg(a + 16 + 3 * i), x1 = __ldg(a + 17 + 3 * i), x2 = __ldg(a + 18 + 3 * i);
#pragma unroll
        for (int o = 0; o < 8; o++) {
            float w = __ldg(Wqv + i * 8 + o);
            qv[3 * o + 0] = fmaf(w, x0, qv[3 * o + 0]);
            qv[3 * o + 1] = fmaf(w, x1, qv[3 * o + 1]);
            qv[3 * o + 2] = fmaf(w, x2, qv[3 * o + 2]);
        }
    }
    float* q = d_qnode + n * DD;
#pragma unroll
    for (int o = 0; o < 16; o++) q[o] = qs[o];
#pragma unroll
    for (int c = 0; c < 24; c++) q[16 + c] = qv[c];
}

template <bool IS_K>
__global__ void __launch_bounds__(TCB, 1) k_edge_mma(
    const float* __restrict__ atom, const float* __restrict__ ef,
    const float* __restrict__ sh, const int* __restrict__ ei,
    const float* __restrict__ W1, const float* __restrict__ B1,
    const float* __restrict__ W2, const float* __restrict__ B2,
    int n_edges)
{
    extern __shared__ float sm[];
    float* sW1 = sm + OFF_W1;
    float* sB1 = sm + OFF_B1;
    float* sB2 = sm + OFF_B2;
    float* stage = sm + OFF_STG;
    unsigned* pAH = (unsigned*)(sm + OFF_PAH);
    unsigned* pAL = (unsigned*)(sm + OFF_PAL);
    unsigned* pBH = (unsigned*)(sm + OFF_PBH);
    unsigned* pBL = (unsigned*)(sm + OFF_PBL);
    float* Dsm = sm + OFF_DSM;

    const int t = threadIdx.x;
    const int w = t >> 5, lane = t & 31;
    const int er = t & 127;     // edge row (MLP / epilogue)
    const int qf = t >> 7;      // quarter index (0..3)

    for (int i = t; i < 1024; i += TCB) sW1[i] = __ldg(W1 + i);
    if (t < 32) sB1[t] = __ldg(B1 + t);
    for (int i = t; i < WND; i += TCB) sB2[i] = __ldg(B2 + i);
    // W2 [32][640] -> k-pair-packed bf16 hi/lo: pB[n][p] = (W2[2p][n], W2[2p+1][n])
    for (int idx = t; idx < WND * 16; idx += TCB) {
        int n = idx >> 4, p = idx & 15;
        float w0 = __ldg(W2 + (2 * p) * WND + n);
        float w1 = __ldg(W2 + (2 * p + 1) * WND + n);
        __nv_bfloat16 h0 = __float2bfloat16(w0), h1 = __float2bfloat16(w1);
        float l0 = w0 - __bfloat162float(h0), l1 = w1 - __bfloat162float(h1);
        pBH[n * 20 + p] = (unsigned)__bfloat16_as_ushort(h0) | ((unsigned)__bfloat16_as_ushort(h1) << 16);
        pBL[n * 20 + p] = pkbf(l0, l1);
    }
    __syncthreads();

    // ldmatrix per-lane address components
    const unsigned aHu = s2u(pAH), aLu = s2u(pAL);
    const unsigned bHu = s2u(pBH), bLu = s2u(pBL);
    const int arow = lane & 15, ahw = lane >> 4;
    const int brow = lane & 7,  bhw = lane >> 3;
    const unsigned aoff = (unsigned)(arow * 80 + ahw * 16);
    const unsigned boff = (unsigned)(brow * 80 + bhw * 16);
    const int rg = w & 3, cg = w >> 2;   // 4 row-groups x 4 col-groups

    const int n_chunks = (n_edges + EC - 1) / EC;
    for (int c = blockIdx.x; c < n_chunks; c += gridDim.x) {
        const int c0 = c * EC;
        // stage ef
        {
            const int lim = n_edges * HED;
            for (int l = t; l < EC * HED; l += TCB) {
                int g = c0 * HED + l;
                stage[(l >> 5) * 65 + (l & 31)] = (g < lim) ? __ldg(ef + g) : 0.f;
            }
        }
        __syncthreads();

        // MLP1: thread computes h[qf*8 .. qf*8+8) for edge er
        {
            float hreg[8];
            const float* myef = stage + er * 65;
            const float* b1h = sB1 + qf * 8;
#pragma unroll
            for (int j = 0; j < 8; j++) hreg[j] = b1h[j];
#pragma unroll 4
            for (int i = 0; i < 32; i++) {
                float x = myef[i];
#pragma unroll
                for (int j2 = 0; j2 < 2; j2++) {
                    float4 r = *reinterpret_cast<const float4*>(sW1 + i * 32 + qf * 8 + 4 * j2);
                    hreg[4 * j2 + 0] = fmaf(x, r.x, hreg[4 * j2 + 0]);
                    hreg[4 * j2 + 1] = fmaf(x, r.y, hreg[4 * j2 + 1]);
                    hreg[4 * j2 + 2] = fmaf(x, r.z, hreg[4 * j2 + 2]);
                    hreg[4 * j2 + 3] = fmaf(x, r.w, hreg[4 * j2 + 3]);
                }
            }
#pragma unroll
            for (int j = 0; j < 8; j++) hreg[j] = fmaxf(hreg[j], 0.f);
#pragma unroll
            for (int p = 0; p < 4; p++) {
                float x = hreg[2 * p], y = hreg[2 * p + 1];
                __nv_bfloat16 hx = __float2bfloat16(x), hy = __float2bfloat16(y);
                pAH[er * 20 + qf * 4 + p] =
                    (unsigned)__bfloat16_as_ushort(hx) | ((unsigned)__bfloat16_as_ushort(hy) << 16);
                pAL[er * 20 + qf * 4 + p] = pkbf(x - __bfloat162float(hx), y - __bfloat162float(hy));
            }
        }
        __syncthreads();   // all ef reads done; pA complete

        // phase C: quarter 0 writes atom features + scalar coefs into stage row er
        const int e = c0 + er;
        const bool valid = e < n_edges;
        const int ecl = valid ? e : (n_edges - 1);
        int src = 0;
        if (qf == 0) {
            float shs = 0.f, s0 = 0.f, s1 = 0.f, s2 = 0.f;
            float* stw = stage + er * 65;
            if (valid) {
                int dst = __ldg(ei + e);
                src = __ldg(ei + n_edges + e);
                float4 s4 = __ldg(reinterpret_cast<const float4*>(sh) + e);
                shs = s4.x; s0 = s4.y; s1 = s4.z; s2 = s4.w;
                const float4* ar = reinterpret_cast<const float4*>(atom + dst * DD);
#pragma unroll
                for (int i = 0; i < 10; i++) {
                    float4 v = __ldg(ar + i);
                    stw[4 * i] = v.x; stw[4 * i + 1] = v.y;
                    stw[4 * i + 2] = v.z; stw[4 * i + 3] = v.w;
                }
            } else {
#pragma unroll
                for (int i = 0; i < 40; i++) stw[i] = 0.f;
            }
#pragma unroll
            for (int i = 0; i < 16; i++) stw[40 + i] = stw[i] * shs;
#pragma unroll
            for (int i = 0; i < 8; i++) {
                const float* xv = stw + 16 + 3 * i;
                stw[56 + i] = kC110 * (xv[0] * s0 + xv[1] * s1 + xv[2] * s2);
            }
        }
        // every thread fetches sh for its row (L1-cached, clamped)
        float4 shv = __ldg(reinterpret_cast<const float4*>(sh) + ecl);
        if (!valid) { shv.x = 0.f; shv.y = 0.f; shv.z = 0.f; shv.w = 0.f; }
        __syncthreads();

        const float* st = stage + er * 65;
        float os[16], ov[24];
#pragma unroll
        for (int o = 0; o < 16; o++) os[o] = 0.f;
#pragma unroll
        for (int o = 0; o < 24; o++) ov[o] = 0.f;

        for (int tile = 0; tile < 5; tile++) {
            // ---- mma: warp (rg, cg) covers mt {2rg, 2rg+1} x cols [cg*32, cg*32+32)
            unsigned bh[4][4], bl[4][4];
#pragma unroll
            for (int nn = 0; nn < 4; nn++) {
                unsigned nbase = (unsigned)((tile * 128 + cg * 32 + nn * 8) * 80);
                ldm4(bh[nn][0], bh[nn][1], bh[nn][2], bh[nn][3], bHu + nbase + boff);
                ldm4(bl[nn][0], bl[nn][1], bl[nn][2], bl[nn][3], bLu + nbase + boff);
            }
#pragma unroll
            for (int mtl = 0; mtl < 2; mtl++) {
                const int mt = rg * 2 + mtl;
                const int r0 = mt * 16 + (lane >> 2);
                unsigned mbase = (unsigned)(mt * 16 * 80);
                unsigned ah0, ah1, ah2, ah3, ah4, ah5, ah6, ah7;
                unsigned al0, al1, al2, al3, al4, al5, al6, al7;
                ldm4(ah0, ah1, ah2, ah3, aHu + mbase + aoff);
                ldm4(ah4, ah5, ah6, ah7, aHu + mbase + aoff + 32);
                ldm4(al0, al1, al2, al3, aLu + mbase + aoff);
                ldm4(al4, al5, al6, al7, aLu + mbase + aoff + 32);
#pragma unroll
                for (int nn = 0; nn < 4; nn++) {
                    float a0 = 0.f, a1 = 0.f, a2 = 0.f, a3 = 0.f;
                    float b0 = 0.f, b1 = 0.f, b2 = 0.f, b3 = 0.f;
                    mma16816(a0, a1, a2, a3, ah0, ah1, ah2, ah3, bh[nn][0], bh[nn][1]);
                    mma16816(a0, a1, a2, a3, ah4, ah5, ah6, ah7, bh[nn][2], bh[nn][3]);
                    mma16816(a0, a1, a2, a3, ah0, ah1, ah2, ah3, bl[nn][0], bl[nn][1]);
                    mma16816(b0, b1, b2, b3, ah4, ah5, ah6, ah7, bl[nn][2], bl[nn][3]);
                    mma16816(b0, b1, b2, b3, al0, al1, al2, al3, bh[nn][0], bh[nn][1]);
                    mma16816(b0, b1, b2, b3, al4, al5, al6, al7, bh[nn][2], bh[nn][3]);
                    int col = cg * 32 + nn * 8 + (lane & 3) * 2;
                    float* r0p = Dsm + r0 * DST + col;
                    float* r1p = Dsm + (r0 + 8) * DST + col;
                    r0p[0] = a0 + b0; r0p[1] = a1 + b1;
                    r1p[0] = a2 + b2; r1p[1] = a3 + b3;
                }
            }
            __syncthreads();

            // ---- epilogue: thread (er, qf) consumes a quarter of row er's columns
            const float* myD = Dsm + er * DST;
            if (tile < 3) {
#pragma unroll
                for (int q2 = 0; q2 < 2; q2++) {
                    int ib = qf * 2 + q2;
                    float aa = st[40 + tile * 8 + ib];
#pragma unroll
                    for (int o4 = 0; o4 < 4; o4++) {
                        float4 d4 = *reinterpret_cast<const float4*>(myD + ib * 16 + 4 * o4);
                        float4 b4 = *reinterpret_cast<const float4*>(sB2 + tile * 128 + ib * 16 + 4 * o4);
                        os[4 * o4 + 0] = fmaf(d4.x + b4.x, aa, os[4 * o4 + 0]);
                        os[4 * o4 + 1] = fmaf(d4.y + b4.y, aa, os[4 * o4 + 1]);
                        os[4 * o4 + 2] = fmaf(d4.z + b4.z, aa, os[4 * o4 + 2]);
                        os[4 * o4 + 3] = fmaf(d4.w + b4.w, aa, os[4 * o4 + 3]);
                    }
                }
            } else {
                float shs = shv.x, s0 = shv.y, s1 = shv.z, s2 = shv.w;
#pragma unroll
                for (int q4 = 0; q4 < 4; q4++) {
                    int ii = qf * 4 + q4;
                    int i3 = (tile - 3) * 16 + ii;
                    float m0, m1, m2;
                    if (i3 < 16) {
                        float x = st[i3];
                        m0 = x * s0; m1 = x * s1; m2 = x * s2;
                    } else if (i3 < 24) {
                        const float* xv = st + 16 + 3 * (i3 - 16);
                        m0 = xv[0] * shs; m1 = xv[1] * shs; m2 = xv[2] * shs;
                    } else {
                        const float* xv = st + 16 + 3 * (i3 - 24);
                        m0 = kC111 * (xv[1] * s2 - xv[2] * s1);
                        m1 = kC111 * (xv[2] * s0 - xv[0] * s2);
                        m2 = kC111 * (xv[0] * s1 - xv[1] * s0);
                    }
                    float4 d4a = *reinterpret_cast<const float4*>(myD + ii * 8);
                    float4 d4b = *reinterpret_cast<const float4*>(myD + ii * 8 + 4);
                    float dv[8] = {d4a.x, d4a.y, d4a.z, d4a.w, d4b.x, d4b.y, d4b.z, d4b.w};
#pragma unroll
                    for (int oo = 0; oo < 8; oo++) {
                        int n = 384 + i3 * 8 + oo;
                        float wv = dv[oo] + sB2[n];
                        ov[3 * oo + 0] = fmaf(wv, m0, ov[3 * oo + 0]);
                        ov[3 * oo + 1] = fmaf(wv, m1, ov[3 * oo + 1]);
                        ov[3 * oo + 2] = fmaf(wv, m2, ov[3 * oo + 2]);
                    }
                }
            }
            __syncthreads();
        }

        // merge quarters: qf 1..3 write partials, qf 0 adds and emits
        if (qf != 0) {
            float* mrow = Dsm + er * DST + (qf - 1) * 44;
#pragma unroll
            for (int o = 0; o < 16; o++) mrow[o] = os[o];
#pragma unroll
            for (int cc = 0; cc < 24; cc++) mrow[16 + cc] = ov[cc];
        }
        __syncthreads();
        if (qf == 0 && valid) {
            const float* mrow = Dsm + er * DST;
#pragma unroll
            for (int o = 0; o < 16; o++) os[o] += mrow[o] + mrow[44 + o] + mrow[88 + o];
#pragma unroll
            for (int cc = 0; cc < 24; cc++) ov[cc] += mrow[16 + cc] + mrow[60 + cc] + mrow[104 + cc];

            if (IS_K) {
                const float* q = d_qnode + src * DD;
                float attn = 0.f;
#pragma unroll
                for (int o = 0; o < 16; o++) attn = fmaf(os[o], __ldg(q + o), attn);
#pragma unroll
                for (int cc = 0; cc < 24; cc++) attn = fmaf(ov[cc], __ldg(q + 16 + cc), attn);
                d_attn[e] = attn;
                atomicMax(&d_nmax[src], encf(attn));
            } else {
#pragma unroll
                for (int o = 0; o < 16; o++) d_vedge[o * n_edges + e] = os[o];
#pragma unroll
                for (int cc = 0; cc < 24; cc++) d_vedge[(16 + cc) * n_edges + e] = ov[cc];
            }
        }
        __syncthreads();
    }
}

__global__ void k_soft(const int* __restrict__ ei, int n_edges) {
    int e = blockIdx.x * blockDim.x + threadIdx.x;
    if (e >= n_edges) return;
    int src = __ldg(ei + n_edges + e);
    float m = decf(d_nmax[src]);
    float a = expf(d_attn[e] - m);
    atomicAdd(&d_denom[src], a);
    float* u = d_upd + src * DD;
#pragma unroll
    for (int c = 0; c < DD; c++)
        atomicAdd(u + c, a * d_vedge[c * n_edges + e]);
}

__global__ void k_stats(const float* __restrict__ atom, int n_nodes) {
    __shared__ float red[40];
    int t = threadIdx.x;
    if (t < 40) red[t] = 0.f;
    __syncthreads();
    int n = blockIdx.x * blockDim.x + t;
    float y[40];
    if (n < n_nodes) {
        float den = d_denom[n];
        float inv = den > 0.f ? 1.f / den : 0.f;
#pragma unroll
        for (int c = 0; c < 40; c++) {
            y[c] = atom[n * DD + c] + d_upd[n * DD + c] * inv;
            d_ybuf[n * DD + c] = y[c];
        }
    } else {
#pragma unroll
        for (int c = 0; c < 40; c++) y[c] = 0.f;
    }
    const unsigned full = 0xffffffffu;
#pragma unroll
    for (int c = 0; c < 16; c++) {
        float v = y[c], v2 = v * v;
#pragma unroll
        for (int o = 16; o > 0; o >>= 1) {
            v  += __shfl_down_sync(full, v, o);
            v2 += __shfl_down_sync(full, v2, o);
        }
        if ((t & 31) == 0) { atomicAdd(&red[c], v); atomicAdd(&red[16 + c], v2); }
    }
#pragma unroll
    for (int i = 0; i < 8; i++) {
        float v = y[16 + 3 * i] * y[16 + 3 * i] + y[17 + 3 * i] * y[17 + 3 * i]
                + y[18 + 3 * i] * y[18 + 3 * i];
#pragma unroll
        for (int o = 16; o > 0; o >>= 1) v += __shfl_down_sync(full, v, o);
        if ((t & 31) == 0) atomicAdd(&red[32 + i], v);
    }
    __syncthreads();
    if (t < 40) atomicAdd(&d_gstats[t], red[t]);
}

__global__ void k_bn(const float* __restrict__ ws, const float* __restrict__ bs,
                     const float* __restrict__ wv, int n_nodes) {
    int t = threadIdx.x;
    float N = (float)n_nodes;
    if (t < 16) {
        float mu  = d_gstats[t] / N;
        float var = d_gstats[16 + t] / N - mu * mu;
        float A = __ldg(ws + t) / sqrtf(var + EPSV);
        d_bnp[t] = A;
        d_bnp[16 + t] = __ldg(bs + t) - mu * A;
    } else if (t < 24) {
        int i = t - 16;
        float norm = d_gstats[32 + i] / (3.f * N);
        d_bnp[32 + i] = __ldg(wv + i) / sqrtf(norm + EPSV);
    }
}

__global__ void k_out(float* __restrict__ out, int n_nodes) {
    int idx = blockIdx.x * blockDim.x + threadIdx.x;
    if (idx >= n_nodes * DD) return;
    int c = idx % DD;
    float y = d_ybuf[idx];
    out[idx] = (c < 16) ? (y * d_bnp[c] + d_bnp[16 + c])
                        : (y * d_bnp[32 + (c - 16) / 3]);
}

__global__ void k_copy(const float* __restrict__ src, float* __restrict__ dst, int n4) {
    int i = blockIdx.x * blockDim.x + threadIdx.x;
    if (i < n4)
        reinterpret_cast<float4*>(dst)[i] = __ldg(reinterpret_cast<const float4*>(src) + i);
}

extern "C" void kernel_launch(void* const* d_in, const int* in_sizes, int n_in,
                              void* d_out, int out_size) {
    const float* atom = (const float*)d_in[0];
    const float* ef   = (const float*)d_in[1];
    const float* sh   = (const float*)d_in[2];
    const float* Wqs  = (const float*)d_in[3];
    const float* Wqv  = (const float*)d_in[4];
    const float* kw1  = (const float*)d_in[5];
    const float* kb1  = (const float*)d_in[6];
    const float* kw2  = (const float*)d_in[7];
    const float* kb2  = (const float*)d_in[8];
    const float* vw1  = (const float*)d_in[9];
    const float* vb1  = (const float*)d_in[10];
    const float* vw2  = (const float*)d_in[11];
    const float* vb2  = (const float*)d_in[12];
    const float* bnws = (const float*)d_in[13];
    const float* bnbs = (const float*)d_in[14];
    const float* bnwv = (const float*)d_in[15];
    const int*   ei   = (const int*)d_in[16];

    int n_nodes = in_sizes[0] / DD;
    int n_edges = in_sizes[1] / HED;
    float* out = (float*)d_out;

    cudaFuncSetAttribute(k_edge_mma<true>,  cudaFuncAttributeMaxDynamicSharedMemorySize, SM_TC);
    cudaFuncSetAttribute(k_edge_mma<false>, cudaFuncAttributeMaxDynamicSharedMemorySize, SM_TC);

    k_init<<<(n_nodes * DD + 255) / 256, 256>>>(n_nodes);
    k_qnode<<<(n_nodes + 255) / 256, 256>>>(atom, Wqs, Wqv, n_nodes);

    k_edge_mma<true><<<148, TCB, SM_TC>>>(atom, ef, sh, ei, kw1, kb1, kw2, kb2, n_edges);
    k_edge_mma<false><<<148, TCB, SM_TC>>>(atom, ef, sh, ei, vw1, vb1, vw2, vb2, n_edges);

    k_soft<<<(n_edges + 255) / 256, 256>>>(ei, n_edges);
    k_stats<<<(n_nodes + 255) / 256, 256>>>(atom, n_nodes);
    k_bn<<<1, 64>>>(bnws, bnbs, bnwv, n_nodes);
    k_out<<<(n_nodes * DD + 255) / 256, 256>>>(out, n_nodes);

    int n4 = (n_edges * HED) / 4;
    k_copy<<<(n4 + 255) / 256, 256>>>(ef, out + n_nodes * DD, n4);
}